// round 1
// baseline (speedup 1.0000x reference)
#include <cuda_runtime.h>
#include <math.h>

// Problem constants
#define Bb 32
#define Ll 512
#define Ee 512
#define RR (Bb*Ll)      // 16384 rows (b,l)
#define KE (5*Ee)       // 2560 unfold K
#define EPSV 1e-3f

// Scratch (static device memory; no allocations allowed)
__device__ float g_l[RR*Ee];        // l (pre-BN then post BN+elu, in place)
__device__ float g_q[RR*Ee];        // q2
__device__ float g_k[RR*Ee];        // k2
__device__ float g_w[Bb*Ll*Ll];     // attention, TRANSPOSED layout wT[b,k,q]
__device__ float g_o[RR*Ee];        // pre-BN5 output
__device__ float g_s[10*Ee];        // stats: [sum1,sq1,sum2,sq2,sum3,sq3,sum5,sq5,sum4,sq4]

// ---------------------------------------------------------------------------
// Reductions
// ---------------------------------------------------------------------------
__device__ __forceinline__ float blockReduceSum(float v, float* sh) {
    const int t = threadIdx.x;
    #pragma unroll
    for (int o = 16; o > 0; o >>= 1) v += __shfl_xor_sync(0xffffffffu, v, o);
    if ((t & 31) == 0) sh[t >> 5] = v;
    __syncthreads();
    if (t < 32) {
        v = (t < (int)(blockDim.x >> 5)) ? sh[t] : 0.f;
        #pragma unroll
        for (int o = 16; o > 0; o >>= 1) v += __shfl_xor_sync(0xffffffffu, v, o);
        if (t == 0) sh[0] = v;
    }
    __syncthreads();
    float r = sh[0];
    __syncthreads();
    return r;
}

__device__ __forceinline__ float blockReduceMax(float v, float* sh) {
    const int t = threadIdx.x;
    #pragma unroll
    for (int o = 16; o > 0; o >>= 1) v = fmaxf(v, __shfl_xor_sync(0xffffffffu, v, o));
    if ((t & 31) == 0) sh[t >> 5] = v;
    __syncthreads();
    if (t < 32) {
        v = (t < (int)(blockDim.x >> 5)) ? sh[t] : -INFINITY;
        #pragma unroll
        for (int o = 16; o > 0; o >>= 1) v = fmaxf(v, __shfl_xor_sync(0xffffffffu, v, o));
        if (t == 0) sh[0] = v;
    }
    __syncthreads();
    float r = sh[0];
    __syncthreads();
    return r;
}

// ---------------------------------------------------------------------------
// Small utility kernels
// ---------------------------------------------------------------------------
__global__ void k_zero(float* p, int n) {
    int i = blockIdx.x * blockDim.x + threadIdx.x;
    if (i < n) p[i] = 0.f;
}

// Per-column sum/sumsq over [RR, 512] matrix. block=512 threads (one per col),
// each block handles 128 rows; fully coalesced; atomic accumulate.
__global__ void k_colstats(const float* __restrict__ X, float* sum, float* sumsq) {
    const int c = threadIdx.x;
    const size_t r0 = (size_t)blockIdx.x * 128;
    float s = 0.f, q = 0.f;
    #pragma unroll 4
    for (int r = 0; r < 128; r++) {
        float v = X[(r0 + r) * 512 + c];
        s += v; q += v * v;
    }
    atomicAdd(&sum[c], s);
    atomicAdd(&sumsq[c], q);
}

// BN4 stats: per k over (b,q).  wT layout: elem (b,k,q) at (b*512+k)*512+q.
__global__ void k_rowstats4(const float* __restrict__ Wt, float* sum, float* sumsq) {
    const int k = blockIdx.x;
    float s = 0.f, q = 0.f;
    for (int idx = threadIdx.x; idx < RR; idx += 256) {
        const int b = idx >> 9, qq = idx & 511;
        float v = Wt[((size_t)(b * Ll + k) << 9) + qq];
        s += v; q += v * v;
    }
    __shared__ float sh[32];
    s = blockReduceSum(s, sh);
    q = blockReduceSum(q, sh);
    if (threadIdx.x == 0) { sum[k] = s; sumsq[k] = q; }
}

// Elementwise BN (training-mode, stats from sum/sumsq over N=RR) + ELU
__global__ void k_bn_elu(const float* __restrict__ X, float* __restrict__ Y,
                         const float* __restrict__ sum, const float* __restrict__ sumsq,
                         const float* __restrict__ g, const float* __restrict__ bt) {
    const float invN = 1.f / (float)RR;
    const size_t total = (size_t)RR * Ee;
    for (size_t i = (size_t)blockIdx.x * blockDim.x + threadIdx.x; i < total;
         i += (size_t)gridDim.x * blockDim.x) {
        const int c = (int)(i & 511);
        const float mean = sum[c] * invN;
        const float var = sumsq[c] * invN - mean * mean;
        const float sc = g[c] * rsqrtf(var + EPSV);
        const float y = (X[i] - mean) * sc + bt[c];
        Y[i] = y > 0.f ? y : expm1f(y);
    }
}

// BN4 + softmax over q (contiguous 512-rows of wT). One block per (b,k).
__global__ void k_bn_softmax(float* __restrict__ Wt,
                             const float* __restrict__ sum, const float* __restrict__ sumsq,
                             const float* __restrict__ g4, const float* __restrict__ b4) {
    const int bk = blockIdx.x;          // b*512 + k
    const int k = bk & 511;
    float* row = Wt + ((size_t)bk << 9);
    const float invN = 1.f / (float)RR;
    const float mean = sum[k] * invN;
    const float var = sumsq[k] * invN - mean * mean;
    const float sc = g4[k] * rsqrtf(var + EPSV);
    const float shf = b4[k] - mean * sc;
    const int t = threadIdx.x;
    float x0 = row[t] * sc + shf;
    float x1 = row[t + 256] * sc + shf;
    __shared__ float sh[32];
    float mx = blockReduceMax(fmaxf(x0, x1), sh);
    float e0 = expf(x0 - mx), e1 = expf(x1 - mx);
    float tot = blockReduceSum(e0 + e1, sh);
    float inv = 1.f / tot;
    row[t] = e0 * inv;
    row[t + 256] = e1 * inv;
}

// ---------------------------------------------------------------------------
// GEMM kernels: 128x128 C tile, BK=16, 256 threads, 8x8 per thread
// (register tile split as 4+4 rows/cols for conflict-free LDS.128)
// ---------------------------------------------------------------------------

// GEMM1: C[RR,512] = unfold(m1) @ f + kb.  A gathered from m1 with zero pad.
__global__ void __launch_bounds__(256) k_gemm1(const float* __restrict__ m1,
                                               const float* __restrict__ f,
                                               const float* __restrict__ kb,
                                               float* __restrict__ C) {
    __shared__ float As[16][128];
    __shared__ float Bs[16][128];
    float acc[8][8] = {{0.f}};
    const int tid = threadIdx.x;
    const int tx = tid & 15, ty = tid >> 4;
    const int br = blockIdx.y << 7, bc = blockIdx.x << 7;
    const int lm = tid >> 2, lk4 = (tid & 3) << 2;
    const int lkb = tid >> 5, ln4 = (tid & 31) << 2;

    for (int k0 = 0; k0 < KE; k0 += 16) {
        #pragma unroll
        for (int rr = 0; rr < 2; rr++) {
            const int m = lm + (rr << 6);
            const int row = br + m;
            const int b = row >> 9, l = row & 511;
            const int kg = k0 + lk4;
            const int sl = l + (kg >> 9) - 2;        // window shift - S
            float4 v = make_float4(0.f, 0.f, 0.f, 0.f);
            if ((unsigned)sl < 512u)
                v = *(const float4*)(m1 + ((size_t)((b << 9) + sl) << 9) + (kg & 511));
            As[lk4 + 0][m] = v.x; As[lk4 + 1][m] = v.y;
            As[lk4 + 2][m] = v.z; As[lk4 + 3][m] = v.w;
        }
        #pragma unroll
        for (int rr = 0; rr < 2; rr++) {
            const int kk = lkb + (rr << 3);
            *(float4*)&Bs[kk][ln4] = *(const float4*)(f + (size_t)(k0 + kk) * Ee + bc + ln4);
        }
        __syncthreads();
        #pragma unroll
        for (int kk = 0; kk < 16; kk++) {
            float a[8], b2[8];
            *(float4*)&a[0] = *(const float4*)&As[kk][ty << 2];
            *(float4*)&a[4] = *(const float4*)&As[kk][64 + (ty << 2)];
            *(float4*)&b2[0] = *(const float4*)&Bs[kk][tx << 2];
            *(float4*)&b2[4] = *(const float4*)&Bs[kk][64 + (tx << 2)];
            #pragma unroll
            for (int i = 0; i < 8; i++)
                #pragma unroll
                for (int j = 0; j < 8; j++)
                    acc[i][j] += a[i] * b2[j];
        }
        __syncthreads();
    }
    #pragma unroll
    for (int i = 0; i < 8; i++) {
        const int row = br + ((i < 4) ? (ty << 2) + i : 64 + (ty << 2) + i - 4);
        const int l = row & 511;
        #pragma unroll
        for (int jj = 0; jj < 2; jj++) {
            const int col = bc + (jj << 6) + (tx << 2);
            float4 bv = *(const float4*)(kb + (size_t)l * Ee + col);
            float4 v;
            v.x = acc[i][jj * 4 + 0] + bv.x; v.y = acc[i][jj * 4 + 1] + bv.y;
            v.z = acc[i][jj * 4 + 2] + bv.z; v.w = acc[i][jj * 4 + 3] + bv.w;
            *(float4*)(C + (size_t)row * Ee + col) = v;
        }
    }
}

// NN GEMM: C[RR,512] = A[RR,512] @ Bm[512,512] + bias[(row%512),col]
__global__ void __launch_bounds__(256) k_gemm_nn(const float* __restrict__ A,
                                                 const float* __restrict__ Bm,
                                                 const float* __restrict__ bias,
                                                 float* __restrict__ C) {
    __shared__ float As[16][128];
    __shared__ float Bs[16][128];
    float acc[8][8] = {{0.f}};
    const int tid = threadIdx.x;
    const int tx = tid & 15, ty = tid >> 4;
    const int br = blockIdx.y << 7, bc = blockIdx.x << 7;
    const int lm = tid >> 2, lk4 = (tid & 3) << 2;
    const int lkb = tid >> 5, ln4 = (tid & 31) << 2;

    for (int k0 = 0; k0 < 512; k0 += 16) {
        #pragma unroll
        for (int rr = 0; rr < 2; rr++) {
            const int m = lm + (rr << 6);
            float4 v = *(const float4*)(A + (size_t)(br + m) * 512 + k0 + lk4);
            As[lk4 + 0][m] = v.x; As[lk4 + 1][m] = v.y;
            As[lk4 + 2][m] = v.z; As[lk4 + 3][m] = v.w;
        }
        #pragma unroll
        for (int rr = 0; rr < 2; rr++) {
            const int kk = lkb + (rr << 3);
            *(float4*)&Bs[kk][ln4] = *(const float4*)(Bm + (size_t)(k0 + kk) * 512 + bc + ln4);
        }
        __syncthreads();
        #pragma unroll
        for (int kk = 0; kk < 16; kk++) {
            float a[8], b2[8];
            *(float4*)&a[0] = *(const float4*)&As[kk][ty << 2];
            *(float4*)&a[4] = *(const float4*)&As[kk][64 + (ty << 2)];
            *(float4*)&b2[0] = *(const float4*)&Bs[kk][tx << 2];
            *(float4*)&b2[4] = *(const float4*)&Bs[kk][64 + (tx << 2)];
            #pragma unroll
            for (int i = 0; i < 8; i++)
                #pragma unroll
                for (int j = 0; j < 8; j++)
                    acc[i][j] += a[i] * b2[j];
        }
        __syncthreads();
    }
    #pragma unroll
    for (int i = 0; i < 8; i++) {
        const int row = br + ((i < 4) ? (ty << 2) + i : 64 + (ty << 2) + i - 4);
        const int l = row & 511;
        #pragma unroll
        for (int jj = 0; jj < 2; jj++) {
            const int col = bc + (jj << 6) + (tx << 2);
            float4 bv = *(const float4*)(bias + (size_t)l * 512 + col);
            float4 v;
            v.x = acc[i][jj * 4 + 0] + bv.x; v.y = acc[i][jj * 4 + 1] + bv.y;
            v.z = acc[i][jj * 4 + 2] + bv.z; v.w = acc[i][jj * 4 + 3] + bv.w;
            *(float4*)(C + (size_t)row * 512 + col) = v;
        }
    }
}

// Batched NT GEMM: per batch z, C[k,q] = sum_e A[k,e]*Bm[q,e] + wb[q,k]
// A = k2[z], Bm = q2[z], C = wT[z].
__global__ void __launch_bounds__(256) k_gemm_nt(const float* __restrict__ Ain,
                                                 const float* __restrict__ Bin,
                                                 const float* __restrict__ wb,
                                                 float* __restrict__ Cout) {
    const int bz = blockIdx.z;
    const float* A = Ain + (size_t)bz * Ll * Ee;
    const float* Bm = Bin + (size_t)bz * Ll * Ee;
    float* C = Cout + (size_t)bz * Ll * Ll;
    __shared__ float As[16][128];
    __shared__ float Bs[16][128];
    float acc[8][8] = {{0.f}};
    const int tid = threadIdx.x;
    const int tx = tid & 15, ty = tid >> 4;
    const int br = blockIdx.y << 7, bc = blockIdx.x << 7;
    const int lm = tid >> 2, lk4 = (tid & 3) << 2;

    for (int k0 = 0; k0 < 512; k0 += 16) {
        #pragma unroll
        for (int rr = 0; rr < 2; rr++) {
            const int m = lm + (rr << 6);
            float4 v = *(const float4*)(A + (size_t)(br + m) * 512 + k0 + lk4);
            As[lk4 + 0][m] = v.x; As[lk4 + 1][m] = v.y;
            As[lk4 + 2][m] = v.z; As[lk4 + 3][m] = v.w;
            float4 w = *(const float4*)(Bm + (size_t)(bc + m) * 512 + k0 + lk4);
            Bs[lk4 + 0][m] = w.x; Bs[lk4 + 1][m] = w.y;
            Bs[lk4 + 2][m] = w.z; Bs[lk4 + 3][m] = w.w;
        }
        __syncthreads();
        #pragma unroll
        for (int kk = 0; kk < 16; kk++) {
            float a[8], b2[8];
            *(float4*)&a[0] = *(const float4*)&As[kk][ty << 2];
            *(float4*)&a[4] = *(const float4*)&As[kk][64 + (ty << 2)];
            *(float4*)&b2[0] = *(const float4*)&Bs[kk][tx << 2];
            *(float4*)&b2[4] = *(const float4*)&Bs[kk][64 + (tx << 2)];
            #pragma unroll
            for (int i = 0; i < 8; i++)
                #pragma unroll
                for (int j = 0; j < 8; j++)
                    acc[i][j] += a[i] * b2[j];
        }
        __syncthreads();
    }
    #pragma unroll
    for (int i = 0; i < 8; i++) {
        const int row = br + ((i < 4) ? (ty << 2) + i : 64 + (ty << 2) + i - 4);  // k
        #pragma unroll
        for (int jj = 0; jj < 2; jj++) {
            const int col = bc + (jj << 6) + (tx << 2);                           // q
            float4 v;
            v.x = acc[i][jj * 4 + 0] + wb[(size_t)(col + 0) * 512 + row];
            v.y = acc[i][jj * 4 + 1] + wb[(size_t)(col + 1) * 512 + row];
            v.z = acc[i][jj * 4 + 2] + wb[(size_t)(col + 2) * 512 + row];
            v.w = acc[i][jj * 4 + 3] + wb[(size_t)(col + 3) * 512 + row];
            *(float4*)(C + (size_t)row * 512 + col) = v;
        }
    }
}

// Batched TN GEMM: per batch z, C[q,e] = sum_k A[k,q]*Bm[k,e]
// A = softmaxed wT[z] ([k,q]), Bm = l[z], C = out_pre[z].
__global__ void __launch_bounds__(256) k_gemm_tn(const float* __restrict__ Ain,
                                                 const float* __restrict__ Bin,
                                                 float* __restrict__ Cout) {
    const int bz = blockIdx.z;
    const float* A = Ain + (size_t)bz * Ll * Ll;
    const float* Bm = Bin + (size_t)bz * Ll * Ee;
    float* C = Cout + (size_t)bz * Ll * Ee;
    __shared__ float As[16][128];
    __shared__ float Bs[16][128];
    float acc[8][8] = {{0.f}};
    const int tid = threadIdx.x;
    const int tx = tid & 15, ty = tid >> 4;
    const int br = blockIdx.y << 7, bc = blockIdx.x << 7;
    const int lk = tid >> 5, lc4 = (tid & 31) << 2;

    for (int k0 = 0; k0 < 512; k0 += 16) {
        #pragma unroll
        for (int rr = 0; rr < 2; rr++) {
            const int kk = lk + (rr << 3);
            *(float4*)&As[kk][lc4] = *(const float4*)(A + (size_t)(k0 + kk) * 512 + br + lc4);
            *(float4*)&Bs[kk][lc4] = *(const float4*)(Bm + (size_t)(k0 + kk) * 512 + bc + lc4);
        }
        __syncthreads();
        #pragma unroll
        for (int kk = 0; kk < 16; kk++) {
            float a[8], b2[8];
            *(float4*)&a[0] = *(const float4*)&As[kk][ty << 2];
            *(float4*)&a[4] = *(const float4*)&As[kk][64 + (ty << 2)];
            *(float4*)&b2[0] = *(const float4*)&Bs[kk][tx << 2];
            *(float4*)&b2[4] = *(const float4*)&Bs[kk][64 + (tx << 2)];
            #pragma unroll
            for (int i = 0; i < 8; i++)
                #pragma unroll
                for (int j = 0; j < 8; j++)
                    acc[i][j] += a[i] * b2[j];
        }
        __syncthreads();
    }
    #pragma unroll
    for (int i = 0; i < 8; i++) {
        const int row = br + ((i < 4) ? (ty << 2) + i : 64 + (ty << 2) + i - 4);
        #pragma unroll
        for (int jj = 0; jj < 2; jj++) {
            const int col = bc + (jj << 6) + (tx << 2);
            float4 v;
            v.x = acc[i][jj * 4 + 0]; v.y = acc[i][jj * 4 + 1];
            v.z = acc[i][jj * 4 + 2]; v.w = acc[i][jj * 4 + 3];
            *(float4*)(C + (size_t)row * 512 + col) = v;
        }
    }
}

// ---------------------------------------------------------------------------
// Launcher
// ---------------------------------------------------------------------------
extern "C" void kernel_launch(void* const* d_in, const int* in_sizes, int n_in,
                              void* d_out, int out_size) {
    const float* m1 = (const float*)d_in[0];
    const float* f  = (const float*)d_in[1];
    const float* wq = (const float*)d_in[2];
    const float* wk = (const float*)d_in[3];
    const float* qb = (const float*)d_in[4];
    const float* kb = (const float*)d_in[5];
    const float* wb = (const float*)d_in[6];
    const float* g1 = (const float*)d_in[7];  const float* b1 = (const float*)d_in[8];
    const float* g2 = (const float*)d_in[9];  const float* b2 = (const float*)d_in[10];
    const float* g3 = (const float*)d_in[11]; const float* b3 = (const float*)d_in[12];
    const float* g4 = (const float*)d_in[13]; const float* b4 = (const float*)d_in[14];
    const float* g5 = (const float*)d_in[15]; const float* b5 = (const float*)d_in[16];

    float *pl, *pq, *pk, *pw, *po, *ps;
    cudaGetSymbolAddress((void**)&pl, g_l);
    cudaGetSymbolAddress((void**)&pq, g_q);
    cudaGetSymbolAddress((void**)&pk, g_k);
    cudaGetSymbolAddress((void**)&pw, g_w);
    cudaGetSymbolAddress((void**)&po, g_o);
    cudaGetSymbolAddress((void**)&ps, g_s);

    const dim3 gemm_grid(4, 128);        // N/128 x M/128
    const dim3 gemm_grid_b(4, 4, 32);    // batched 512x512
    const int T = 256;

    // zero atomically-accumulated stat buffers (4 pairs = 4096 floats)
    k_zero<<<16, 256>>>(ps, 8 * Ee);

    // 1) l_pre = unfold(m1) @ f + kb
    k_gemm1<<<gemm_grid, T>>>(m1, f, kb, pl);
    // BN1 + ELU (in place)
    k_colstats<<<128, 512>>>(pl, ps + 0 * Ee, ps + 1 * Ee);
    k_bn_elu<<<2048, T>>>(pl, pl, ps + 0 * Ee, ps + 1 * Ee, g1, b1);

    // 2) q2 / k2
    k_gemm_nn<<<gemm_grid, T>>>(pl, wq, qb, pq);
    k_gemm_nn<<<gemm_grid, T>>>(pl, wk, kb, pk);
    k_colstats<<<128, 512>>>(pq, ps + 2 * Ee, ps + 3 * Ee);
    k_colstats<<<128, 512>>>(pk, ps + 4 * Ee, ps + 5 * Ee);
    k_bn_elu<<<2048, T>>>(pq, pq, ps + 2 * Ee, ps + 3 * Ee, g2, b2);
    k_bn_elu<<<2048, T>>>(pk, pk, ps + 4 * Ee, ps + 5 * Ee, g3, b3);

    // 3) wT[b,k,q] = k2 @ q2^T + wb[q,k]
    k_gemm_nt<<<gemm_grid_b, T>>>(pk, pq, wb, pw);
    // BN4 stats (per k over b,q) then BN4 + softmax over q (contiguous)
    k_rowstats4<<<512, 256>>>(pw, ps + 8 * Ee, ps + 9 * Ee);
    k_bn_softmax<<<16384, 256>>>(pw, ps + 8 * Ee, ps + 9 * Ee, g4, b4);

    // 4) out_pre[q,e] = sum_k wT[k,q] * l[k,e]
    k_gemm_tn<<<gemm_grid_b, T>>>(pw, pl, po);
    // BN5 + ELU -> d_out
    k_colstats<<<128, 512>>>(po, ps + 6 * Ee, ps + 7 * Ee);
    k_bn_elu<<<2048, T>>>(po, (float*)d_out, ps + 6 * Ee, ps + 7 * Ee, g5, b5);
}

// round 2
// speedup vs baseline: 1.9917x; 1.9917x over previous
#include <cuda_runtime.h>
#include <math.h>
#include <stdint.h>

// Problem constants
#define Bb 32
#define Ll 512
#define Ee 512
#define RR (Bb*Ll)      // 16384 rows (b,l)
#define KE (5*Ee)       // 2560 unfold K
#define EPSV 1e-3f
#define PADW 136        // smem row pitch (uint32) -> conflict-free mma frag loads

// Scratch (static device memory; no allocations allowed)
__device__ float g_l[RR*Ee];
__device__ float g_q[RR*Ee];
__device__ float g_k[RR*Ee];
__device__ float g_w[Bb*Ll*Ll];     // attention, TRANSPOSED layout wT[b,k,q]
__device__ float g_o[RR*Ee];
__device__ float g_wbT[Ll*Ll];      // wb transposed: wbT[k*512+q] = wb[q*512+k]
__device__ float g_s[10*Ee];

// ---------------------------------------------------------------------------
// tf32 helpers
// ---------------------------------------------------------------------------
__device__ __forceinline__ uint32_t f2tf32(float x) {
    uint32_t r;
    asm("cvt.rna.tf32.f32 %0, %1;" : "=r"(r) : "f"(x));
    return r;
}

// warp-level mma core: consumes As[16][PADW], Bs[16][PADW] (k-major),
// accumulates into c[2][8][4]. Warp tile 32(m) x 64(n).
__device__ __forceinline__ void mma_core(const uint32_t (*As)[PADW],
                                         const uint32_t (*Bs)[PADW],
                                         float c[2][8][4],
                                         int g, int t, int wm, int wn) {
    #pragma unroll
    for (int ks = 0; ks < 2; ks++) {
        const int kb = ks * 8;
        uint32_t a[2][4], b[8][2];
        #pragma unroll
        for (int mt = 0; mt < 2; mt++) {
            const int m = wm + mt * 16 + g;
            a[mt][0] = As[kb + t][m];
            a[mt][1] = As[kb + t][m + 8];
            a[mt][2] = As[kb + t + 4][m];
            a[mt][3] = As[kb + t + 4][m + 8];
        }
        #pragma unroll
        for (int nt = 0; nt < 8; nt++) {
            const int n = wn + nt * 8 + g;
            b[nt][0] = Bs[kb + t][n];
            b[nt][1] = Bs[kb + t + 4][n];
        }
        #pragma unroll
        for (int mt = 0; mt < 2; mt++)
            #pragma unroll
            for (int nt = 0; nt < 8; nt++)
                asm volatile(
                    "mma.sync.aligned.m16n8k8.row.col.f32.tf32.tf32.f32 "
                    "{%0,%1,%2,%3},{%4,%5,%6,%7},{%8,%9},{%0,%1,%2,%3};"
                    : "+f"(c[mt][nt][0]), "+f"(c[mt][nt][1]),
                      "+f"(c[mt][nt][2]), "+f"(c[mt][nt][3])
                    : "r"(a[mt][0]), "r"(a[mt][1]), "r"(a[mt][2]), "r"(a[mt][3]),
                      "r"(b[nt][0]), "r"(b[nt][1]));
    }
}

// ---------------------------------------------------------------------------
// Reductions
// ---------------------------------------------------------------------------
__device__ __forceinline__ float blockReduceSum(float v, float* sh) {
    const int t = threadIdx.x;
    #pragma unroll
    for (int o = 16; o > 0; o >>= 1) v += __shfl_xor_sync(0xffffffffu, v, o);
    if ((t & 31) == 0) sh[t >> 5] = v;
    __syncthreads();
    if (t < 32) {
        v = (t < (int)(blockDim.x >> 5)) ? sh[t] : 0.f;
        #pragma unroll
        for (int o = 16; o > 0; o >>= 1) v += __shfl_xor_sync(0xffffffffu, v, o);
        if (t == 0) sh[0] = v;
    }
    __syncthreads();
    float r = sh[0];
    __syncthreads();
    return r;
}

__device__ __forceinline__ float blockReduceMax(float v, float* sh) {
    const int t = threadIdx.x;
    #pragma unroll
    for (int o = 16; o > 0; o >>= 1) v = fmaxf(v, __shfl_xor_sync(0xffffffffu, v, o));
    if ((t & 31) == 0) sh[t >> 5] = v;
    __syncthreads();
    if (t < 32) {
        v = (t < (int)(blockDim.x >> 5)) ? sh[t] : -INFINITY;
        #pragma unroll
        for (int o = 16; o > 0; o >>= 1) v = fmaxf(v, __shfl_xor_sync(0xffffffffu, v, o));
        if (t == 0) sh[0] = v;
    }
    __syncthreads();
    float r = sh[0];
    __syncthreads();
    return r;
}

// ---------------------------------------------------------------------------
// Utility kernels (unchanged from R1)
// ---------------------------------------------------------------------------
__global__ void k_zero(float* p, int n) {
    int i = blockIdx.x * blockDim.x + threadIdx.x;
    if (i < n) p[i] = 0.f;
}

__global__ void k_transpose(const float* __restrict__ src, float* __restrict__ dst) {
    __shared__ float tile[32][33];
    const int bx = blockIdx.x << 5, by = blockIdx.y << 5;
    #pragma unroll
    for (int j = 0; j < 4; j++)
        tile[threadIdx.y + j * 8][threadIdx.x] =
            src[(size_t)(by + threadIdx.y + j * 8) * 512 + bx + threadIdx.x];
    __syncthreads();
    #pragma unroll
    for (int j = 0; j < 4; j++)
        dst[(size_t)(bx + threadIdx.y + j * 8) * 512 + by + threadIdx.x] =
            tile[threadIdx.x][threadIdx.y + j * 8];
}

__global__ void k_colstats(const float* __restrict__ X, float* sum, float* sumsq) {
    const int c = threadIdx.x;
    const size_t r0 = (size_t)blockIdx.x * 128;
    float s = 0.f, q = 0.f;
    #pragma unroll 4
    for (int r = 0; r < 128; r++) {
        float v = X[(r0 + r) * 512 + c];
        s += v; q += v * v;
    }
    atomicAdd(&sum[c], s);
    atomicAdd(&sumsq[c], q);
}

__global__ void k_rowstats4(const float* __restrict__ Wt, float* sum, float* sumsq) {
    const int k = blockIdx.x;
    float s = 0.f, q = 0.f;
    for (int idx = threadIdx.x; idx < RR; idx += 256) {
        const int b = idx >> 9, qq = idx & 511;
        float v = Wt[((size_t)(b * Ll + k) << 9) + qq];
        s += v; q += v * v;
    }
    __shared__ float sh[32];
    s = blockReduceSum(s, sh);
    q = blockReduceSum(q, sh);
    if (threadIdx.x == 0) { sum[k] = s; sumsq[k] = q; }
}

__global__ void k_bn_elu(const float* __restrict__ X, float* __restrict__ Y,
                         const float* __restrict__ sum, const float* __restrict__ sumsq,
                         const float* __restrict__ g, const float* __restrict__ bt) {
    const float invN = 1.f / (float)RR;
    const size_t total = (size_t)RR * Ee;
    for (size_t i = (size_t)blockIdx.x * blockDim.x + threadIdx.x; i < total;
         i += (size_t)gridDim.x * blockDim.x) {
        const int c = (int)(i & 511);
        const float mean = sum[c] * invN;
        const float var = sumsq[c] * invN - mean * mean;
        const float sc = g[c] * rsqrtf(var + EPSV);
        const float y = (X[i] - mean) * sc + bt[c];
        Y[i] = y > 0.f ? y : expm1f(y);
    }
}

__global__ void k_bn_softmax(float* __restrict__ Wt,
                             const float* __restrict__ sum, const float* __restrict__ sumsq,
                             const float* __restrict__ g4, const float* __restrict__ b4) {
    const int bk = blockIdx.x;
    const int k = bk & 511;
    float* row = Wt + ((size_t)bk << 9);
    const float invN = 1.f / (float)RR;
    const float mean = sum[k] * invN;
    const float var = sumsq[k] * invN - mean * mean;
    const float sc = g4[k] * rsqrtf(var + EPSV);
    const float shf = b4[k] - mean * sc;
    const int t = threadIdx.x;
    float x0 = row[t] * sc + shf;
    float x1 = row[t + 256] * sc + shf;
    __shared__ float sh[32];
    float mx = blockReduceMax(fmaxf(x0, x1), sh);
    float e0 = expf(x0 - mx), e1 = expf(x1 - mx);
    float tot = blockReduceSum(e0 + e1, sh);
    float inv = 1.f / tot;
    row[t] = e0 * inv;
    row[t + 256] = e1 * inv;
}

// ---------------------------------------------------------------------------
// Tensor-core GEMMs: 128x128 C tile, BK=16, 256 threads (8 warps 4x2),
// warp tile 32x64, mma.m16n8k8.tf32.
// ---------------------------------------------------------------------------

// GEMM1: C[RR,512] = unfold(m1) @ f + kb   (A gathered from m1, zero-padded)
__global__ void __launch_bounds__(256) k_gemm1(const float* __restrict__ m1,
                                               const float* __restrict__ f,
                                               const float* __restrict__ kb,
                                               float* __restrict__ C) {
    __shared__ uint32_t As[16][PADW];
    __shared__ uint32_t Bs[16][PADW];
    float c[2][8][4] = {{{0.f}}};
    const int tid = threadIdx.x;
    const int lane = tid & 31, wid = tid >> 5;
    const int g = lane >> 2, t = lane & 3;
    const int wm = (wid & 3) << 5, wn = (wid >> 2) << 6;
    const int br = blockIdx.y << 7, bc = blockIdx.x << 7;
    const int lm = tid >> 2, lk4 = (tid & 3) << 2;
    const int lkb = tid >> 5, ln4 = (tid & 31) << 2;

    for (int k0 = 0; k0 < KE; k0 += 16) {
        #pragma unroll
        for (int rr = 0; rr < 2; rr++) {
            const int m = lm + (rr << 6);
            const int row = br + m;
            const int b = row >> 9, l = row & 511;
            const int kg = k0 + lk4;
            const int sl = l + (kg >> 9) - 2;
            float4 v = make_float4(0.f, 0.f, 0.f, 0.f);
            if ((unsigned)sl < 512u)
                v = *(const float4*)(m1 + ((size_t)((b << 9) + sl) << 9) + (kg & 511));
            As[lk4 + 0][m] = f2tf32(v.x); As[lk4 + 1][m] = f2tf32(v.y);
            As[lk4 + 2][m] = f2tf32(v.z); As[lk4 + 3][m] = f2tf32(v.w);
        }
        #pragma unroll
        for (int rr = 0; rr < 2; rr++) {
            const int kk = lkb + (rr << 3);
            float4 v = *(const float4*)(f + (size_t)(k0 + kk) * Ee + bc + ln4);
            uint4 u = make_uint4(f2tf32(v.x), f2tf32(v.y), f2tf32(v.z), f2tf32(v.w));
            *(uint4*)&Bs[kk][ln4] = u;
        }
        __syncthreads();
        mma_core(As, Bs, c, g, t, wm, wn);
        __syncthreads();
    }
    #pragma unroll
    for (int mt = 0; mt < 2; mt++)
        #pragma unroll
        for (int i = 0; i < 2; i++) {
            const int row = br + wm + mt * 16 + g + 8 * i;
            const int l = row & 511;
            #pragma unroll
            for (int nt = 0; nt < 8; nt++) {
                const int col = bc + wn + nt * 8 + 2 * t;
                float2 bv = *(const float2*)(kb + (size_t)l * 512 + col);
                float2 v;
                v.x = c[mt][nt][2 * i + 0] + bv.x;
                v.y = c[mt][nt][2 * i + 1] + bv.y;
                *(float2*)(C + (size_t)row * 512 + col) = v;
            }
        }
}

// NN GEMM: C[RR,512] = A[RR,512] @ Bm[512,512] + bias[(row%512),col]
__global__ void __launch_bounds__(256) k_gemm_nn(const float* __restrict__ A,
                                                 const float* __restrict__ Bm,
                                                 const float* __restrict__ bias,
                                                 float* __restrict__ C) {
    __shared__ uint32_t As[16][PADW];
    __shared__ uint32_t Bs[16][PADW];
    float c[2][8][4] = {{{0.f}}};
    const int tid = threadIdx.x;
    const int lane = tid & 31, wid = tid >> 5;
    const int g = lane >> 2, t = lane & 3;
    const int wm = (wid & 3) << 5, wn = (wid >> 2) << 6;
    const int br = blockIdx.y << 7, bc = blockIdx.x << 7;
    const int lm = tid >> 2, lk4 = (tid & 3) << 2;
    const int lkb = tid >> 5, ln4 = (tid & 31) << 2;

    for (int k0 = 0; k0 < 512; k0 += 16) {
        #pragma unroll
        for (int rr = 0; rr < 2; rr++) {
            const int m = lm + (rr << 6);
            float4 v = *(const float4*)(A + (size_t)(br + m) * 512 + k0 + lk4);
            As[lk4 + 0][m] = f2tf32(v.x); As[lk4 + 1][m] = f2tf32(v.y);
            As[lk4 + 2][m] = f2tf32(v.z); As[lk4 + 3][m] = f2tf32(v.w);
        }
        #pragma unroll
        for (int rr = 0; rr < 2; rr++) {
            const int kk = lkb + (rr << 3);
            float4 v = *(const float4*)(Bm + (size_t)(k0 + kk) * 512 + bc + ln4);
            uint4 u = make_uint4(f2tf32(v.x), f2tf32(v.y), f2tf32(v.z), f2tf32(v.w));
            *(uint4*)&Bs[kk][ln4] = u;
        }
        __syncthreads();
        mma_core(As, Bs, c, g, t, wm, wn);
        __syncthreads();
    }
    #pragma unroll
    for (int mt = 0; mt < 2; mt++)
        #pragma unroll
        for (int i = 0; i < 2; i++) {
            const int row = br + wm + mt * 16 + g + 8 * i;
            const int l = row & 511;
            #pragma unroll
            for (int nt = 0; nt < 8; nt++) {
                const int col = bc + wn + nt * 8 + 2 * t;
                float2 bv = *(const float2*)(bias + (size_t)l * 512 + col);
                float2 v;
                v.x = c[mt][nt][2 * i + 0] + bv.x;
                v.y = c[mt][nt][2 * i + 1] + bv.y;
                *(float2*)(C + (size_t)row * 512 + col) = v;
            }
        }
}

// Batched NT GEMM: per batch z, C[k,q] = sum_e k2[k,e]*q2[q,e] + wbT[k,q]
__global__ void __launch_bounds__(256) k_gemm_nt(const float* __restrict__ Ain,
                                                 const float* __restrict__ Bin,
                                                 const float* __restrict__ wbT,
                                                 float* __restrict__ Cout) {
    const int bz = blockIdx.z;
    const float* A = Ain + (size_t)bz * Ll * Ee;
    const float* Bm = Bin + (size_t)bz * Ll * Ee;
    float* C = Cout + (size_t)bz * Ll * Ll;
    __shared__ uint32_t As[16][PADW];
    __shared__ uint32_t Bs[16][PADW];
    float c[2][8][4] = {{{0.f}}};
    const int tid = threadIdx.x;
    const int lane = tid & 31, wid = tid >> 5;
    const int g = lane >> 2, t = lane & 3;
    const int wm = (wid & 3) << 5, wn = (wid >> 2) << 6;
    const int br = blockIdx.y << 7, bc = blockIdx.x << 7;
    const int lm = tid >> 2, lk4 = (tid & 3) << 2;

    for (int k0 = 0; k0 < 512; k0 += 16) {
        #pragma unroll
        for (int rr = 0; rr < 2; rr++) {
            const int m = lm + (rr << 6);
            float4 v = *(const float4*)(A + (size_t)(br + m) * 512 + k0 + lk4);
            As[lk4 + 0][m] = f2tf32(v.x); As[lk4 + 1][m] = f2tf32(v.y);
            As[lk4 + 2][m] = f2tf32(v.z); As[lk4 + 3][m] = f2tf32(v.w);
            float4 w = *(const float4*)(Bm + (size_t)(bc + m) * 512 + k0 + lk4);
            Bs[lk4 + 0][m] = f2tf32(w.x); Bs[lk4 + 1][m] = f2tf32(w.y);
            Bs[lk4 + 2][m] = f2tf32(w.z); Bs[lk4 + 3][m] = f2tf32(w.w);
        }
        __syncthreads();
        mma_core(As, Bs, c, g, t, wm, wn);
        __syncthreads();
    }
    #pragma unroll
    for (int mt = 0; mt < 2; mt++)
        #pragma unroll
        for (int i = 0; i < 2; i++) {
            const int row = br + wm + mt * 16 + g + 8 * i;   // k
            #pragma unroll
            for (int nt = 0; nt < 8; nt++) {
                const int col = bc + wn + nt * 8 + 2 * t;    // q
                float2 bv = *(const float2*)(wbT + (size_t)row * 512 + col);
                float2 v;
                v.x = c[mt][nt][2 * i + 0] + bv.x;
                v.y = c[mt][nt][2 * i + 1] + bv.y;
                *(float2*)(C + (size_t)row * 512 + col) = v;
            }
        }
}

// Batched TN GEMM: per batch z, C[q,e] = sum_k wT[k,q]*l[k,e]
__global__ void __launch_bounds__(256) k_gemm_tn(const float* __restrict__ Ain,
                                                 const float* __restrict__ Bin,
                                                 float* __restrict__ Cout) {
    const int bz = blockIdx.z;
    const float* A = Ain + (size_t)bz * Ll * Ll;
    const float* Bm = Bin + (size_t)bz * Ll * Ee;
    float* C = Cout + (size_t)bz * Ll * Ee;
    __shared__ uint32_t As[16][PADW];
    __shared__ uint32_t Bs[16][PADW];
    float c[2][8][4] = {{{0.f}}};
    const int tid = threadIdx.x;
    const int lane = tid & 31, wid = tid >> 5;
    const int g = lane >> 2, t = lane & 3;
    const int wm = (wid & 3) << 5, wn = (wid >> 2) << 6;
    const int br = blockIdx.y << 7, bc = blockIdx.x << 7;
    const int lk = tid >> 5, lc4 = (tid & 31) << 2;

    for (int k0 = 0; k0 < 512; k0 += 16) {
        #pragma unroll
        for (int rr = 0; rr < 2; rr++) {
            const int kk = lk + (rr << 3);
            float4 v = *(const float4*)(A + (size_t)(k0 + kk) * 512 + br + lc4);
            uint4 u = make_uint4(f2tf32(v.x), f2tf32(v.y), f2tf32(v.z), f2tf32(v.w));
            *(uint4*)&As[kk][lc4] = u;
            float4 w = *(const float4*)(Bm + (size_t)(k0 + kk) * 512 + bc + lc4);
            uint4 u2 = make_uint4(f2tf32(w.x), f2tf32(w.y), f2tf32(w.z), f2tf32(w.w));
            *(uint4*)&Bs[kk][lc4] = u2;
        }
        __syncthreads();
        mma_core(As, Bs, c, g, t, wm, wn);
        __syncthreads();
    }
    #pragma unroll
    for (int mt = 0; mt < 2; mt++)
        #pragma unroll
        for (int i = 0; i < 2; i++) {
            const int row = br + wm + mt * 16 + g + 8 * i;
            #pragma unroll
            for (int nt = 0; nt < 8; nt++) {
                const int col = bc + wn + nt * 8 + 2 * t;
                float2 v;
                v.x = c[mt][nt][2 * i + 0];
                v.y = c[mt][nt][2 * i + 1];
                *(float2*)(C + (size_t)row * 512 + col) = v;
            }
        }
}

// ---------------------------------------------------------------------------
// Launcher
// ---------------------------------------------------------------------------
extern "C" void kernel_launch(void* const* d_in, const int* in_sizes, int n_in,
                              void* d_out, int out_size) {
    const float* m1 = (const float*)d_in[0];
    const float* f  = (const float*)d_in[1];
    const float* wq = (const float*)d_in[2];
    const float* wk = (const float*)d_in[3];
    const float* qb = (const float*)d_in[4];
    const float* kb = (const float*)d_in[5];
    const float* wb = (const float*)d_in[6];
    const float* g1 = (const float*)d_in[7];  const float* b1 = (const float*)d_in[8];
    const float* g2 = (const float*)d_in[9];  const float* b2 = (const float*)d_in[10];
    const float* g3 = (const float*)d_in[11]; const float* b3 = (const float*)d_in[12];
    const float* g4 = (const float*)d_in[13]; const float* b4 = (const float*)d_in[14];
    const float* g5 = (const float*)d_in[15]; const float* b5 = (const float*)d_in[16];

    float *pl, *pq, *pk, *pw, *po, *ps, *pwbT;
    cudaGetSymbolAddress((void**)&pl, g_l);
    cudaGetSymbolAddress((void**)&pq, g_q);
    cudaGetSymbolAddress((void**)&pk, g_k);
    cudaGetSymbolAddress((void**)&pw, g_w);
    cudaGetSymbolAddress((void**)&po, g_o);
    cudaGetSymbolAddress((void**)&ps, g_s);
    cudaGetSymbolAddress((void**)&pwbT, g_wbT);

    const dim3 gemm_grid(4, 128);
    const dim3 gemm_grid_b(4, 4, 32);
    const int T = 256;

    k_zero<<<16, 256>>>(ps, 8 * Ee);
    k_transpose<<<dim3(16, 16), dim3(32, 8)>>>(wb, pwbT);

    // 1) l_pre = unfold(m1) @ f + kb ; BN1 + ELU
    k_gemm1<<<gemm_grid, T>>>(m1, f, kb, pl);
    k_colstats<<<128, 512>>>(pl, ps + 0 * Ee, ps + 1 * Ee);
    k_bn_elu<<<2048, T>>>(pl, pl, ps + 0 * Ee, ps + 1 * Ee, g1, b1);

    // 2) q2 / k2
    k_gemm_nn<<<gemm_grid, T>>>(pl, wq, qb, pq);
    k_gemm_nn<<<gemm_grid, T>>>(pl, wk, kb, pk);
    k_colstats<<<128, 512>>>(pq, ps + 2 * Ee, ps + 3 * Ee);
    k_colstats<<<128, 512>>>(pk, ps + 4 * Ee, ps + 5 * Ee);
    k_bn_elu<<<2048, T>>>(pq, pq, ps + 2 * Ee, ps + 3 * Ee, g2, b2);
    k_bn_elu<<<2048, T>>>(pk, pk, ps + 4 * Ee, ps + 5 * Ee, g3, b3);

    // 3) wT[b,k,q] = k2 @ q2^T + wbT ; BN4 + softmax over q
    k_gemm_nt<<<gemm_grid_b, T>>>(pk, pq, pwbT, pw);
    k_rowstats4<<<512, 256>>>(pw, ps + 8 * Ee, ps + 9 * Ee);
    k_bn_softmax<<<16384, 256>>>(pw, ps + 8 * Ee, ps + 9 * Ee, g4, b4);

    // 4) out_pre = wT^T @ l ; BN5 + ELU -> d_out
    k_gemm_tn<<<gemm_grid_b, T>>>(pw, pl, po);
    k_colstats<<<128, 512>>>(po, ps + 6 * Ee, ps + 7 * Ee);
    k_bn_elu<<<2048, T>>>(po, (float*)d_out, ps + 6 * Ee, ps + 7 * Ee, g5, b5);
}

// round 5
// speedup vs baseline: 2.5175x; 1.2640x over previous
#include <cuda_runtime.h>
#include <math.h>
#include <stdint.h>

// Problem constants
#define Bb 32
#define Ll 512
#define Ee 512
#define RR (Bb*Ll)      // 16384 rows (b,l)
#define KE (5*Ee)       // 2560 unfold K
#define EPSV 1e-3f
#define PADW 136        // smem row pitch (uint32) -> conflict-free mma frag loads

// Scratch (static device memory; no allocations allowed)
__device__ float g_l[RR*Ee];
__device__ float g_q[RR*Ee];
__device__ float g_k[RR*Ee];
__device__ float g_w[Bb*Ll*Ll];     // attention, TRANSPOSED layout wT[b,k,q]
__device__ float g_o[RR*Ee];
__device__ float g_m1r[RR*Ee];      // tf32-rounded m1
__device__ float g_fr[KE*Ee];       // tf32-rounded f
__device__ float g_wqr[Ee*Ee];
__device__ float g_wkr[Ee*Ee];
__device__ float g_wbT[Ll*Ll];      // wb transposed (fp32 exact)
__device__ float g_s[10*Ee];        // stats pairs

// ---------------------------------------------------------------------------
// tf32 helper
// ---------------------------------------------------------------------------
__device__ __forceinline__ uint32_t f2tf32(float x) {
    uint32_t r;
    asm("cvt.rna.tf32.f32 %0, %1;" : "=r"(r) : "f"(x));
    return r;
}

// warp-level mma core: consumes As[16][PADW], Bs[16][PADW] (k-major, raw fp32
// bits already tf32-rounded), accumulates into c[2][8][4]. Warp tile 32x64.
__device__ __forceinline__ void mma_core(const uint32_t (*As)[PADW],
                                         const uint32_t (*Bs)[PADW],
                                         float c[2][8][4],
                                         int g, int t, int wm, int wn) {
    #pragma unroll
    for (int ks = 0; ks < 2; ks++) {
        const int kb = ks * 8;
        uint32_t a[2][4], b[8][2];
        #pragma unroll
        for (int mt = 0; mt < 2; mt++) {
            const int m = wm + mt * 16 + g;
            a[mt][0] = As[kb + t][m];
            a[mt][1] = As[kb + t][m + 8];
            a[mt][2] = As[kb + t + 4][m];
            a[mt][3] = As[kb + t + 4][m + 8];
        }
        #pragma unroll
        for (int nt = 0; nt < 8; nt++) {
            const int n = wn + nt * 8 + g;
            b[nt][0] = Bs[kb + t][n];
            b[nt][1] = Bs[kb + t + 4][n];
        }
        #pragma unroll
        for (int mt = 0; mt < 2; mt++)
            #pragma unroll
            for (int nt = 0; nt < 8; nt++)
                asm volatile(
                    "mma.sync.aligned.m16n8k8.row.col.f32.tf32.tf32.f32 "
                    "{%0,%1,%2,%3},{%4,%5,%6,%7},{%8,%9},{%0,%1,%2,%3};"
                    : "+f"(c[mt][nt][0]), "+f"(c[mt][nt][1]),
                      "+f"(c[mt][nt][2]), "+f"(c[mt][nt][3])
                    : "r"(a[mt][0]), "r"(a[mt][1]), "r"(a[mt][2]), "r"(a[mt][3]),
                      "r"(b[nt][0]), "r"(b[nt][1]));
    }
}

// ---------------------------------------------------------------------------
// Reductions
// ---------------------------------------------------------------------------
__device__ __forceinline__ float blockReduceSum(float v, float* sh) {
    const int t = threadIdx.x;
    #pragma unroll
    for (int o = 16; o > 0; o >>= 1) v += __shfl_xor_sync(0xffffffffu, v, o);
    if ((t & 31) == 0) sh[t >> 5] = v;
    __syncthreads();
    if (t < 32) {
        v = (t < (int)(blockDim.x >> 5)) ? sh[t] : 0.f;
        #pragma unroll
        for (int o = 16; o > 0; o >>= 1) v += __shfl_xor_sync(0xffffffffu, v, o);
        if (t == 0) sh[0] = v;
    }
    __syncthreads();
    float r = sh[0];
    __syncthreads();
    return r;
}

__device__ __forceinline__ float blockReduceMax(float v, float* sh) {
    const int t = threadIdx.x;
    #pragma unroll
    for (int o = 16; o > 0; o >>= 1) v = fmaxf(v, __shfl_xor_sync(0xffffffffu, v, o));
    if ((t & 31) == 0) sh[t >> 5] = v;
    __syncthreads();
    if (t < 32) {
        v = (t < (int)(blockDim.x >> 5)) ? sh[t] : -INFINITY;
        #pragma unroll
        for (int o = 16; o > 0; o >>= 1) v = fmaxf(v, __shfl_xor_sync(0xffffffffu, v, o));
        if (t == 0) sh[0] = v;
    }
    __syncthreads();
    float r = sh[0];
    __syncthreads();
    return r;
}

// ---------------------------------------------------------------------------
// Utility kernels
// ---------------------------------------------------------------------------
__global__ void k_zero(float* p, int n) {
    int i = blockIdx.x * blockDim.x + threadIdx.x;
    if (i < n) p[i] = 0.f;
}

__global__ void k_round(const float* __restrict__ src, float* __restrict__ dst, int n4) {
    int i = blockIdx.x * blockDim.x + threadIdx.x;
    if (i < n4) {
        float4 v = ((const float4*)src)[i];
        uint4 u = make_uint4(f2tf32(v.x), f2tf32(v.y), f2tf32(v.z), f2tf32(v.w));
        ((uint4*)dst)[i] = u;
    }
}

__global__ void k_transpose(const float* __restrict__ src, float* __restrict__ dst) {
    __shared__ float tile[32][33];
    const int bx = blockIdx.x << 5, by = blockIdx.y << 5;
    #pragma unroll
    for (int j = 0; j < 4; j++)
        tile[threadIdx.y + j * 8][threadIdx.x] =
            src[(size_t)(by + threadIdx.y + j * 8) * 512 + bx + threadIdx.x];
    __syncthreads();
    #pragma unroll
    for (int j = 0; j < 4; j++)
        dst[(size_t)(bx + threadIdx.y + j * 8) * 512 + by + threadIdx.x] =
            tile[threadIdx.x][threadIdx.y + j * 8];
}

// Per-column stats over [RR,512]: grid 512 blocks x 256 thr; block = 32 rows,
// thread covers cols tid and tid+256.
__global__ void __launch_bounds__(256) k_colstats(const float* __restrict__ X,
                                                  float* sum, float* sumsq) {
    const size_t r0 = (size_t)blockIdx.x * 32;
    const int c0 = threadIdx.x, c1 = threadIdx.x + 256;
    const float* base = X + r0 * 512;
    float s0 = 0.f, q0 = 0.f, s1 = 0.f, q1 = 0.f;
    #pragma unroll 8
    for (int r = 0; r < 32; r++) {
        float v0 = base[(size_t)r * 512 + c0];
        float v1 = base[(size_t)r * 512 + c1];
        s0 += v0; q0 += v0 * v0;
        s1 += v1; q1 += v1 * v1;
    }
    atomicAdd(&sum[c0], s0);
    atomicAdd(&sumsq[c0], q0);
    atomicAdd(&sum[c1], s1);
    atomicAdd(&sumsq[c1], q1);
}

// BN4 stats: per k over (b,q). grid (512, 4): block = (k, 8-batch slice).
__global__ void __launch_bounds__(256) k_rowstats4(const float* __restrict__ Wt,
                                                   float* sum, float* sumsq) {
    const int k = blockIdx.x;
    const int b0 = blockIdx.y << 3;
    float s = 0.f, q = 0.f;
    for (int idx = threadIdx.x; idx < 8 * 512; idx += 256) {
        const int b = b0 + (idx >> 9), qq = idx & 511;
        float v = Wt[((size_t)(b * Ll + k) << 9) + qq];
        s += v; q += v * v;
    }
    __shared__ float sh[32];
    s = blockReduceSum(s, sh);
    q = blockReduceSum(q, sh);
    if (threadIdx.x == 0) { atomicAdd(&sum[k], s); atomicAdd(&sumsq[k], q); }
}

// BN + ELU, float4-vectorized. ROUND: store tf32-rounded (for GEMM consumers).
template<bool ROUND>
__global__ void __launch_bounds__(256) k_bn_elu(const float4* __restrict__ X,
                                                float4* __restrict__ Y,
                                                const float4* __restrict__ sum4,
                                                const float4* __restrict__ sumsq4,
                                                const float4* __restrict__ g4,
                                                const float4* __restrict__ bt4) {
    const float invN = 1.f / (float)RR;
    const int total4 = RR * Ee / 4;
    for (int i = blockIdx.x * blockDim.x + threadIdx.x; i < total4;
         i += gridDim.x * blockDim.x) {
        const int c4 = i & 127;
        float4 sm = sum4[c4], sq = sumsq4[c4], gg = g4[c4], bb = bt4[c4];
        float4 v = X[i];
        float m, va, sc, y;
        float4 o;
        m = sm.x * invN; va = sq.x * invN - m * m; sc = gg.x * rsqrtf(va + EPSV);
        y = (v.x - m) * sc + bb.x; o.x = y > 0.f ? y : expm1f(y);
        m = sm.y * invN; va = sq.y * invN - m * m; sc = gg.y * rsqrtf(va + EPSV);
        y = (v.y - m) * sc + bb.y; o.y = y > 0.f ? y : expm1f(y);
        m = sm.z * invN; va = sq.z * invN - m * m; sc = gg.z * rsqrtf(va + EPSV);
        y = (v.z - m) * sc + bb.z; o.z = y > 0.f ? y : expm1f(y);
        m = sm.w * invN; va = sq.w * invN - m * m; sc = gg.w * rsqrtf(va + EPSV);
        y = (v.w - m) * sc + bb.w; o.w = y > 0.f ? y : expm1f(y);
        if (ROUND) {
            uint4 u = make_uint4(f2tf32(o.x), f2tf32(o.y), f2tf32(o.z), f2tf32(o.w));
            ((uint4*)Y)[i] = u;
        } else {
            Y[i] = o;
        }
    }
}

// BN4 + softmax over q (contiguous rows of wT). One block per (b,k).
// Stores tf32-rounded (consumed by gemm_tn).
__global__ void k_bn_softmax(float* __restrict__ Wt,
                             const float* __restrict__ sum, const float* __restrict__ sumsq,
                             const float* __restrict__ g4, const float* __restrict__ b4) {
    const int bk = blockIdx.x;
    const int k = bk & 511;
    float* row = Wt + ((size_t)bk << 9);
    const float invN = 1.f / (float)RR;
    const float mean = sum[k] * invN;
    const float var = sumsq[k] * invN - mean * mean;
    const float sc = g4[k] * rsqrtf(var + EPSV);
    const float shf = b4[k] - mean * sc;
    const int t = threadIdx.x;
    float x0 = row[t] * sc + shf;
    float x1 = row[t + 256] * sc + shf;
    __shared__ float sh[32];
    float mx = blockReduceMax(fmaxf(x0, x1), sh);
    float e0 = expf(x0 - mx), e1 = expf(x1 - mx);
    float tot = blockReduceSum(e0 + e1, sh);
    float inv = 1.f / tot;
    ((uint32_t*)row)[t] = f2tf32(e0 * inv);
    ((uint32_t*)row)[t + 256] = f2tf32(e1 * inv);
}

// ---------------------------------------------------------------------------
// Tensor-core GEMMs: 128x128 C tile, BK=16, 256 threads (8 warps 4x2),
// warp tile 32x64, mma.m16n8k8.tf32, register-staged double-buffered smem,
// one __syncthreads per tile. Operands pre-rounded -> no cvt in hot loops.
// ---------------------------------------------------------------------------

// GEMM1: C[RR,512] = unfold(m1r) @ fr + kb   (A gathered, zero-padded)
__global__ void __launch_bounds__(256, 2) k_gemm1(const float* __restrict__ Ar,
                                                  const float* __restrict__ Br,
                                                  const float* __restrict__ kb,
                                                  float* __restrict__ C) {
    __shared__ uint32_t As[2][16][PADW];
    __shared__ uint32_t Bs[2][16][PADW];
    float c[2][8][4] = {{{0.f}}};
    const int tid = threadIdx.x;
    const int lane = tid & 31, wid = tid >> 5;
    const int g = lane >> 2, t = lane & 3;
    const int wm = (wid & 3) << 5, wn = (wid >> 2) << 6;
    const int br = blockIdx.y << 7, bc = blockIdx.x << 7;
    const int lm = tid >> 2, lk4 = (tid & 3) << 2;
    const int lkb = tid >> 5, ln4 = (tid & 31) << 2;

    // per-thread A row decomposition
    int bA[2], lA[2];
    #pragma unroll
    for (int rr = 0; rr < 2; rr++) {
        const int row = br + lm + (rr << 6);
        bA[rr] = row >> 9; lA[rr] = row & 511;
    }

    // prologue: stage tile 0 into buffer 0
    float4 av[2], bvv[2];
    #pragma unroll
    for (int rr = 0; rr < 2; rr++) {
        const int kg = lk4;
        const int sl = lA[rr] + (kg >> 9) - 2;
        av[rr] = make_float4(0.f, 0.f, 0.f, 0.f);
        if ((unsigned)sl < 512u)
            av[rr] = *(const float4*)(Ar + ((size_t)((bA[rr] << 9) + sl) << 9) + (kg & 511));
        const int kk = lkb + (rr << 3);
        bvv[rr] = *(const float4*)(Br + (size_t)kk * Ee + bc + ln4);
    }
    #pragma unroll
    for (int rr = 0; rr < 2; rr++) {
        const int m = lm + (rr << 6);
        As[0][lk4 + 0][m] = __float_as_uint(av[rr].x);
        As[0][lk4 + 1][m] = __float_as_uint(av[rr].y);
        As[0][lk4 + 2][m] = __float_as_uint(av[rr].z);
        As[0][lk4 + 3][m] = __float_as_uint(av[rr].w);
        const int kk = lkb + (rr << 3);
        *(uint4*)&Bs[0][kk][ln4] = make_uint4(__float_as_uint(bvv[rr].x), __float_as_uint(bvv[rr].y),
                                              __float_as_uint(bvv[rr].z), __float_as_uint(bvv[rr].w));
    }

    const int nIter = KE / 16;
    for (int i = 0; i < nIter; i++) {
        const int buf = i & 1, nb = buf ^ 1;
        __syncthreads();
        const int k1 = (i + 1) << 4;
        if (i + 1 < nIter) {
            #pragma unroll
            for (int rr = 0; rr < 2; rr++) {
                const int kg = k1 + lk4;
                const int sl = lA[rr] + (kg >> 9) - 2;
                av[rr] = make_float4(0.f, 0.f, 0.f, 0.f);
                if ((unsigned)sl < 512u)
                    av[rr] = *(const float4*)(Ar + ((size_t)((bA[rr] << 9) + sl) << 9) + (kg & 511));
                const int kk = lkb + (rr << 3);
                bvv[rr] = *(const float4*)(Br + (size_t)(k1 + kk) * Ee + bc + ln4);
            }
        }
        mma_core(As[buf], Bs[buf], c, g, t, wm, wn);
        if (i + 1 < nIter) {
            #pragma unroll
            for (int rr = 0; rr < 2; rr++) {
                const int m = lm + (rr << 6);
                As[nb][lk4 + 0][m] = __float_as_uint(av[rr].x);
                As[nb][lk4 + 1][m] = __float_as_uint(av[rr].y);
                As[nb][lk4 + 2][m] = __float_as_uint(av[rr].z);
                As[nb][lk4 + 3][m] = __float_as_uint(av[rr].w);
                const int kk = lkb + (rr << 3);
                *(uint4*)&Bs[nb][kk][ln4] = make_uint4(__float_as_uint(bvv[rr].x), __float_as_uint(bvv[rr].y),
                                                       __float_as_uint(bvv[rr].z), __float_as_uint(bvv[rr].w));
            }
        }
    }
    #pragma unroll
    for (int mt = 0; mt < 2; mt++)
        #pragma unroll
        for (int i = 0; i < 2; i++) {
            const int row = br + wm + mt * 16 + g + 8 * i;
            const int l = row & 511;
            #pragma unroll
            for (int nt = 0; nt < 8; nt++) {
                const int col = bc + wn + nt * 8 + 2 * t;
                float2 bv = *(const float2*)(kb + (size_t)l * 512 + col);
                float2 v;
                v.x = c[mt][nt][2 * i + 0] + bv.x;
                v.y = c[mt][nt][2 * i + 1] + bv.y;
                *(float2*)(C + (size_t)row * 512 + col) = v;
            }
        }
}

// Fused NN GEMMs (z=0: q2 = l@wq + qb ; z=1: k2 = l@wk + kb)
__global__ void __launch_bounds__(256, 2) k_gemm_nn(const float* __restrict__ A,
                                                    const float* __restrict__ Bq,
                                                    const float* __restrict__ Bk,
                                                    const float* __restrict__ biasq,
                                                    const float* __restrict__ biask,
                                                    float* __restrict__ Cq,
                                                    float* __restrict__ Ck) {
    const float* Bm = blockIdx.z ? Bk : Bq;
    const float* bias = blockIdx.z ? biask : biasq;
    float* C = blockIdx.z ? Ck : Cq;
    __shared__ uint32_t As[2][16][PADW];
    __shared__ uint32_t Bs[2][16][PADW];
    float c[2][8][4] = {{{0.f}}};
    const int tid = threadIdx.x;
    const int lane = tid & 31, wid = tid >> 5;
    const int g = lane >> 2, t = lane & 3;
    const int wm = (wid & 3) << 5, wn = (wid >> 2) << 6;
    const int br = blockIdx.y << 7, bc = blockIdx.x << 7;
    const int lm = tid >> 2, lk4 = (tid & 3) << 2;
    const int lkb = tid >> 5, ln4 = (tid & 31) << 2;

    float4 av[2], bvv[2];
    #pragma unroll
    for (int rr = 0; rr < 2; rr++) {
        av[rr] = *(const float4*)(A + (size_t)(br + lm + (rr << 6)) * 512 + lk4);
        const int kk = lkb + (rr << 3);
        bvv[rr] = *(const float4*)(Bm + (size_t)kk * 512 + bc + ln4);
    }
    #pragma unroll
    for (int rr = 0; rr < 2; rr++) {
        const int m = lm + (rr << 6);
        As[0][lk4 + 0][m] = __float_as_uint(av[rr].x);
        As[0][lk4 + 1][m] = __float_as_uint(av[rr].y);
        As[0][lk4 + 2][m] = __float_as_uint(av[rr].z);
        As[0][lk4 + 3][m] = __float_as_uint(av[rr].w);
        const int kk = lkb + (rr << 3);
        *(uint4*)&Bs[0][kk][ln4] = make_uint4(__float_as_uint(bvv[rr].x), __float_as_uint(bvv[rr].y),
                                              __float_as_uint(bvv[rr].z), __float_as_uint(bvv[rr].w));
    }

    const int nIter = 32;
    for (int i = 0; i < nIter; i++) {
        const int buf = i & 1, nb = buf ^ 1;
        __syncthreads();
        const int k1 = (i + 1) << 4;
        if (i + 1 < nIter) {
            #pragma unroll
            for (int rr = 0; rr < 2; rr++) {
                av[rr] = *(const float4*)(A + (size_t)(br + lm + (rr << 6)) * 512 + k1 + lk4);
                const int kk = lkb + (rr << 3);
                bvv[rr] = *(const float4*)(Bm + (size_t)(k1 + kk) * 512 + bc + ln4);
            }
        }
        mma_core(As[buf], Bs[buf], c, g, t, wm, wn);
        if (i + 1 < nIter) {
            #pragma unroll
            for (int rr = 0; rr < 2; rr++) {
                const int m = lm + (rr << 6);
                As[nb][lk4 + 0][m] = __float_as_uint(av[rr].x);
                As[nb][lk4 + 1][m] = __float_as_uint(av[rr].y);
                As[nb][lk4 + 2][m] = __float_as_uint(av[rr].z);
                As[nb][lk4 + 3][m] = __float_as_uint(av[rr].w);
                const int kk = lkb + (rr << 3);
                *(uint4*)&Bs[nb][kk][ln4] = make_uint4(__float_as_uint(bvv[rr].x), __float_as_uint(bvv[rr].y),
                                                       __float_as_uint(bvv[rr].z), __float_as_uint(bvv[rr].w));
            }
        }
    }
    #pragma unroll
    for (int mt = 0; mt < 2; mt++)
        #pragma unroll
        for (int i = 0; i < 2; i++) {
            const int row = br + wm + mt * 16 + g + 8 * i;
            const int l = row & 511;
            #pragma unroll
            for (int nt = 0; nt < 8; nt++) {
                const int col = bc + wn + nt * 8 + 2 * t;
                float2 bv = *(const float2*)(bias + (size_t)l * 512 + col);
                float2 v;
                v.x = c[mt][nt][2 * i + 0] + bv.x;
                v.y = c[mt][nt][2 * i + 1] + bv.y;
                *(float2*)(C + (size_t)row * 512 + col) = v;
            }
        }
}

// Batched NT GEMM: per batch z, C[k,q] = sum_e k2[k,e]*q2[q,e] + wbT[k,q]
__global__ void __launch_bounds__(256, 2) k_gemm_nt(const float* __restrict__ Ain,
                                                    const float* __restrict__ Bin,
                                                    const float* __restrict__ wbT,
                                                    float* __restrict__ Cout) {
    const int bz = blockIdx.z;
    const float* A = Ain + (size_t)bz * Ll * Ee;
    const float* Bm = Bin + (size_t)bz * Ll * Ee;
    float* C = Cout + (size_t)bz * Ll * Ll;
    __shared__ uint32_t As[2][16][PADW];
    __shared__ uint32_t Bs[2][16][PADW];
    float c[2][8][4] = {{{0.f}}};
    const int tid = threadIdx.x;
    const int lane = tid & 31, wid = tid >> 5;
    const int g = lane >> 2, t = lane & 3;
    const int wm = (wid & 3) << 5, wn = (wid >> 2) << 6;
    const int br = blockIdx.y << 7, bc = blockIdx.x << 7;
    const int lm = tid >> 2, lk4 = (tid & 3) << 2;

    float4 av[2], bv[2];
    #pragma unroll
    for (int rr = 0; rr < 2; rr++) {
        const int m = lm + (rr << 6);
        av[rr] = *(const float4*)(A + (size_t)(br + m) * 512 + lk4);
        bv[rr] = *(const float4*)(Bm + (size_t)(bc + m) * 512 + lk4);
    }
    #pragma unroll
    for (int rr = 0; rr < 2; rr++) {
        const int m = lm + (rr << 6);
        As[0][lk4 + 0][m] = __float_as_uint(av[rr].x);
        As[0][lk4 + 1][m] = __float_as_uint(av[rr].y);
        As[0][lk4 + 2][m] = __float_as_uint(av[rr].z);
        As[0][lk4 + 3][m] = __float_as_uint(av[rr].w);
        Bs[0][lk4 + 0][m] = __float_as_uint(bv[rr].x);
        Bs[0][lk4 + 1][m] = __float_as_uint(bv[rr].y);
        Bs[0][lk4 + 2][m] = __float_as_uint(bv[rr].z);
        Bs[0][lk4 + 3][m] = __float_as_uint(bv[rr].w);
    }

    const int nIter = 32;
    for (int i = 0; i < nIter; i++) {
        const int buf = i & 1, nb = buf ^ 1;
        __syncthreads();
        const int k1 = (i + 1) << 4;
        if (i + 1 < nIter) {
            #pragma unroll
            for (int rr = 0; rr < 2; rr++) {
                const int m = lm + (rr << 6);
                av[rr] = *(const float4*)(A + (size_t)(br + m) * 512 + k1 + lk4);
                bv[rr] = *(const float4*)(Bm + (size_t)(bc + m) * 512 + k1 + lk4);
            }
        }
        mma_core(As[buf], Bs[buf], c, g, t, wm, wn);
        if (i + 1 < nIter) {
            #pragma unroll
            for (int rr = 0; rr < 2; rr++) {
                const int m = lm + (rr << 6);
                As[nb][lk4 + 0][m] = __float_as_uint(av[rr].x);
                As[nb][lk4 + 1][m] = __float_as_uint(av[rr].y);
                As[nb][lk4 + 2][m] = __float_as_uint(av[rr].z);
                As[nb][lk4 + 3][m] = __float_as_uint(av[rr].w);
                Bs[nb][lk4 + 0][m] = __float_as_uint(bv[rr].x);
                Bs[nb][lk4 + 1][m] = __float_as_uint(bv[rr].y);
                Bs[nb][lk4 + 2][m] = __float_as_uint(bv[rr].z);
                Bs[nb][lk4 + 3][m] = __float_as_uint(bv[rr].w);
            }
        }
    }
    #pragma unroll
    for (int mt = 0; mt < 2; mt++)
        #pragma unroll
        for (int i = 0; i < 2; i++) {
            const int row = br + wm + mt * 16 + g + 8 * i;   // k
            #pragma unroll
            for (int nt = 0; nt < 8; nt++) {
                const int col = bc + wn + nt * 8 + 2 * t;    // q
                float2 bv2 = *(const float2*)(wbT + (size_t)row * 512 + col);
                float2 v;
                v.x = c[mt][nt][2 * i + 0] + bv2.x;
                v.y = c[mt][nt][2 * i + 1] + bv2.y;
                *(float2*)(C + (size_t)row * 512 + col) = v;
            }
        }
}

// Batched TN GEMM: per batch z, C[q,e] = sum_k wT[k,q]*l[k,e]
__global__ void __launch_bounds__(256, 2) k_gemm_tn(const float* __restrict__ Ain,
                                                    const float* __restrict__ Bin,
                                                    float* __restrict__ Cout) {
    const int bz = blockIdx.z;
    const float* A = Ain + (size_t)bz * Ll * Ll;
    const float* Bm = Bin + (size_t)bz * Ll * Ee;
    float* C = Cout + (size_t)bz * Ll * Ee;
    __shared__ uint32_t As[2][16][PADW];
    __shared__ uint32_t Bs[2][16][PADW];
    float c[2][8][4] = {{{0.f}}};
    const int tid = threadIdx.x;
    const int lane = tid & 31, wid = tid >> 5;
    const int g = lane >> 2, t = lane & 3;
    const int wm = (wid & 3) << 5, wn = (wid >> 2) << 6;
    const int br = blockIdx.y << 7, bc = blockIdx.x << 7;
    const int lkb = tid >> 5, ln4 = (tid & 31) << 2;

    float4 av[2], bv[2];
    #pragma unroll
    for (int rr = 0; rr < 2; rr++) {
        const int kk = lkb + (rr << 3);
        av[rr] = *(const float4*)(A + (size_t)kk * 512 + br + ln4);
        bv[rr] = *(const float4*)(Bm + (size_t)kk * 512 + bc + ln4);
    }
    #pragma unroll
    for (int rr = 0; rr < 2; rr++) {
        const int kk = lkb + (rr << 3);
        *(uint4*)&As[0][kk][ln4] = make_uint4(__float_as_uint(av[rr].x), __float_as_uint(av[rr].y),
                                              __float_as_uint(av[rr].z), __float_as_uint(av[rr].w));
        *(uint4*)&Bs[0][kk][ln4] = make_uint4(__float_as_uint(bv[rr].x), __float_as_uint(bv[rr].y),
                                              __float_as_uint(bv[rr].z), __float_as_uint(bv[rr].w));
    }

    const int nIter = 32;
    for (int i = 0; i < nIter; i++) {
        const int buf = i & 1, nb = buf ^ 1;
        __syncthreads();
        const int k1 = (i + 1) << 4;
        if (i + 1 < nIter) {
            #pragma unroll
            for (int rr = 0; rr < 2; rr++) {
                const int kk = lkb + (rr << 3);
                av[rr] = *(const float4*)(A + (size_t)(k1 + kk) * 512 + br + ln4);
                bv[rr] = *(const float4*)(Bm + (size_t)(k1 + kk) * 512 + bc + ln4);
            }
        }
        mma_core(As[buf], Bs[buf], c, g, t, wm, wn);
        if (i + 1 < nIter) {
            #pragma unroll
            for (int rr = 0; rr < 2; rr++) {
                const int kk = lkb + (rr << 3);
                *(uint4*)&As[nb][kk][ln4] = make_uint4(__float_as_uint(av[rr].x), __float_as_uint(av[rr].y),
                                                       __float_as_uint(av[rr].z), __float_as_uint(av[rr].w));
                *(uint4*)&Bs[nb][kk][ln4] = make_uint4(__float_as_uint(bv[rr].x), __float_as_uint(bv[rr].y),
                                                       __float_as_uint(bv[rr].z), __float_as_uint(bv[rr].w));
            }
        }
    }
    #pragma unroll
    for (int mt = 0; mt < 2; mt++)
        #pragma unroll
        for (int i = 0; i < 2; i++) {
            const int row = br + wm + mt * 16 + g + 8 * i;
            #pragma unroll
            for (int nt = 0; nt < 8; nt++) {
                const int col = bc + wn + nt * 8 + 2 * t;
                float2 v;
                v.x = c[mt][nt][2 * i + 0];
                v.y = c[mt][nt][2 * i + 1];
                *(float2*)(C + (size_t)row * 512 + col) = v;
            }
        }
}

// ---------------------------------------------------------------------------
// Launcher
// ---------------------------------------------------------------------------
extern "C" void kernel_launch(void* const* d_in, const int* in_sizes, int n_in,
                              void* d_out, int out_size) {
    const float* m1 = (const float*)d_in[0];
    const float* f  = (const float*)d_in[1];
    const float* wq = (const float*)d_in[2];
    const float* wk = (const float*)d_in[3];
    const float* qb = (const float*)d_in[4];
    const float* kb = (const float*)d_in[5];
    const float* wb = (const float*)d_in[6];
    const float* g1 = (const float*)d_in[7];  const float* b1 = (const float*)d_in[8];
    const float* g2 = (const float*)d_in[9];  const float* b2 = (const float*)d_in[10];
    const float* g3 = (const float*)d_in[11]; const float* b3 = (const float*)d_in[12];
    const float* g4 = (const float*)d_in[13]; const float* b4 = (const float*)d_in[14];
    const float* g5 = (const float*)d_in[15]; const float* b5 = (const float*)d_in[16];

    float *pl, *pq, *pk, *pw, *po, *ps, *pwbT, *pm1r, *pfr, *pwqr, *pwkr;
    cudaGetSymbolAddress((void**)&pl, g_l);
    cudaGetSymbolAddress((void**)&pq, g_q);
    cudaGetSymbolAddress((void**)&pk, g_k);
    cudaGetSymbolAddress((void**)&pw, g_w);
    cudaGetSymbolAddress((void**)&po, g_o);
    cudaGetSymbolAddress((void**)&ps, g_s);
    cudaGetSymbolAddress((void**)&pwbT, g_wbT);
    cudaGetSymbolAddress((void**)&pm1r, g_m1r);
    cudaGetSymbolAddress((void**)&pfr, g_fr);
    cudaGetSymbolAddress((void**)&pwqr, g_wqr);
    cudaGetSymbolAddress((void**)&pwkr, g_wkr);

    const int T = 256;

    // pre-passes
    k_zero<<<20, T>>>(ps, 10 * Ee);
    k_transpose<<<dim3(16, 16), dim3(32, 8)>>>(wb, pwbT);
    k_round<<<8192, T>>>(m1, pm1r, RR * Ee / 4);
    k_round<<<1280, T>>>(f, pfr, KE * Ee / 4);
    k_round<<<256, T>>>(wq, pwqr, Ee * Ee / 4);
    k_round<<<256, T>>>(wk, pwkr, Ee * Ee / 4);

    // 1) l_pre = unfold(m1) @ f + kb ; BN1 + ELU (rounded store)
    k_gemm1<<<dim3(4, 128), T>>>(pm1r, pfr, kb, pl);
    k_colstats<<<512, T>>>(pl, ps + 0 * Ee, ps + 1 * Ee);
    k_bn_elu<true><<<2048, T>>>((const float4*)pl, (float4*)pl,
                                (const float4*)(ps + 0 * Ee), (const float4*)(ps + 1 * Ee),
                                (const float4*)g1, (const float4*)b1);

    // 2) q2 / k2 (fused launch)
    k_gemm_nn<<<dim3(4, 128, 2), T>>>(pl, pwqr, pwkr, qb, kb, pq, pk);
    k_colstats<<<512, T>>>(pq, ps + 2 * Ee, ps + 3 * Ee);
    k_colstats<<<512, T>>>(pk, ps + 4 * Ee, ps + 5 * Ee);
    k_bn_elu<true><<<2048, T>>>((const float4*)pq, (float4*)pq,
                                (const float4*)(ps + 2 * Ee), (const float4*)(ps + 3 * Ee),
                                (const float4*)g2, (const float4*)b2);
    k_bn_elu<true><<<2048, T>>>((const float4*)pk, (float4*)pk,
                                (const float4*)(ps + 4 * Ee), (const float4*)(ps + 5 * Ee),
                                (const float4*)g3, (const float4*)b3);

    // 3) wT[b,k,q] = k2 @ q2^T + wbT ; BN4 + softmax over q (rounded store)
    k_gemm_nt<<<dim3(4, 4, 32), T>>>(pk, pq, pwbT, pw);
    k_rowstats4<<<dim3(512, 4), T>>>(pw, ps + 8 * Ee, ps + 9 * Ee);
    k_bn_softmax<<<16384, T>>>(pw, ps + 8 * Ee, ps + 9 * Ee, g4, b4);

    // 4) out_pre = wT^T @ l ; BN5 + ELU -> d_out (fp32 store)
    k_gemm_tn<<<dim3(4, 4, 32), T>>>(pw, pl, po);
    k_colstats<<<512, T>>>(po, ps + 6 * Ee, ps + 7 * Ee);
    k_bn_elu<false><<<2048, T>>>((const float4*)po, (float4*)d_out,
                                 (const float4*)(ps + 6 * Ee), (const float4*)(ps + 7 * Ee),
                                 (const float4*)g5, (const float4*)b5);
}

// round 6
// speedup vs baseline: 2.6146x; 1.0386x over previous
#include <cuda_runtime.h>
#include <math.h>
#include <stdint.h>

// Problem constants
#define Bb 32
#define Ll 512
#define Ee 512
#define RR (Bb*Ll)      // 16384 rows (b,l)
#define KE (5*Ee)       // 2560 unfold K
#define EPSV 1e-3f
#define PADW 136        // smem row pitch (uint32) -> conflict-free mma frag loads

// Scratch (static device memory; no allocations allowed)
__device__ float g_l[RR*Ee];
__device__ float g_q[RR*Ee];
__device__ float g_k[RR*Ee];
__device__ float g_w[Bb*Ll*Ll];     // attention, TRANSPOSED layout wT[b,k,q]
__device__ float g_o[RR*Ee];
__device__ float g_fr[KE*Ee];       // tf32-rounded f
__device__ float g_wqr[Ee*Ee];
__device__ float g_wkr[Ee*Ee];
__device__ float g_wbT[Ll*Ll];      // wb transposed (fp32 exact)
__device__ float g_s[10*Ee];        // stats pairs

// ---------------------------------------------------------------------------
// tf32 helper
// ---------------------------------------------------------------------------
__device__ __forceinline__ uint32_t f2tf32(float x) {
    uint32_t r;
    asm("cvt.rna.tf32.f32 %0, %1;" : "=r"(r) : "f"(x));
    return r;
}

// warp-level mma core: consumes As[16][PADW], Bs[16][PADW] (k-major, raw fp32
// bits already tf32-rounded), accumulates into c[2][8][4]. Warp tile 32x64.
__device__ __forceinline__ void mma_core(const uint32_t (*As)[PADW],
                                         const uint32_t (*Bs)[PADW],
                                         float c[2][8][4],
                                         int g, int t, int wm, int wn) {
    #pragma unroll
    for (int ks = 0; ks < 2; ks++) {
        const int kb = ks * 8;
        uint32_t a[2][4], b[8][2];
        #pragma unroll
        for (int mt = 0; mt < 2; mt++) {
            const int m = wm + mt * 16 + g;
            a[mt][0] = As[kb + t][m];
            a[mt][1] = As[kb + t][m + 8];
            a[mt][2] = As[kb + t + 4][m];
            a[mt][3] = As[kb + t + 4][m + 8];
        }
        #pragma unroll
        for (int nt = 0; nt < 8; nt++) {
            const int n = wn + nt * 8 + g;
            b[nt][0] = Bs[kb + t][n];
            b[nt][1] = Bs[kb + t + 4][n];
        }
        #pragma unroll
        for (int mt = 0; mt < 2; mt++)
            #pragma unroll
            for (int nt = 0; nt < 8; nt++)
                asm volatile(
                    "mma.sync.aligned.m16n8k8.row.col.f32.tf32.tf32.f32 "
                    "{%0,%1,%2,%3},{%4,%5,%6,%7},{%8,%9},{%0,%1,%2,%3};"
                    : "+f"(c[mt][nt][0]), "+f"(c[mt][nt][1]),
                      "+f"(c[mt][nt][2]), "+f"(c[mt][nt][3])
                    : "r"(a[mt][0]), "r"(a[mt][1]), "r"(a[mt][2]), "r"(a[mt][3]),
                      "r"(b[nt][0]), "r"(b[nt][1]));
    }
}

// Column-stats epilogue reduction: each thread holds cs/cq[16] (16 cols, summed
// over its 4 rows). Lanes sharing t (g = lane>>2) cover the same columns ->
// reduce over g via shfl, lane g==0 atomically accumulates.
__device__ __forceinline__ void colstats_epilogue(float* __restrict__ sum,
                                                  float* __restrict__ sumsq,
                                                  const float cs[16], const float cq[16],
                                                  int g, int t, int bcwn) {
    #pragma unroll
    for (int x = 0; x < 16; x++) {
        float s = cs[x], q = cq[x];
        s += __shfl_xor_sync(0xffffffffu, s, 4);  q += __shfl_xor_sync(0xffffffffu, q, 4);
        s += __shfl_xor_sync(0xffffffffu, s, 8);  q += __shfl_xor_sync(0xffffffffu, q, 8);
        s += __shfl_xor_sync(0xffffffffu, s, 16); q += __shfl_xor_sync(0xffffffffu, q, 16);
        if (g == 0) {
            const int col = bcwn + (x >> 1) * 8 + 2 * t + (x & 1);
            atomicAdd(&sum[col], s);
            atomicAdd(&sumsq[col], q);
        }
    }
}

// ---------------------------------------------------------------------------
// Reductions
// ---------------------------------------------------------------------------
__device__ __forceinline__ float blockReduceSum(float v, float* sh) {
    const int t = threadIdx.x;
    #pragma unroll
    for (int o = 16; o > 0; o >>= 1) v += __shfl_xor_sync(0xffffffffu, v, o);
    if ((t & 31) == 0) sh[t >> 5] = v;
    __syncthreads();
    if (t < 32) {
        v = (t < (int)(blockDim.x >> 5)) ? sh[t] : 0.f;
        #pragma unroll
        for (int o = 16; o > 0; o >>= 1) v += __shfl_xor_sync(0xffffffffu, v, o);
        if (t == 0) sh[0] = v;
    }
    __syncthreads();
    float r = sh[0];
    __syncthreads();
    return r;
}

__device__ __forceinline__ float blockReduceMax(float v, float* sh) {
    const int t = threadIdx.x;
    #pragma unroll
    for (int o = 16; o > 0; o >>= 1) v = fmaxf(v, __shfl_xor_sync(0xffffffffu, v, o));
    if ((t & 31) == 0) sh[t >> 5] = v;
    __syncthreads();
    if (t < 32) {
        v = (t < (int)(blockDim.x >> 5)) ? sh[t] : -INFINITY;
        #pragma unroll
        for (int o = 16; o > 0; o >>= 1) v = fmaxf(v, __shfl_xor_sync(0xffffffffu, v, o));
        if (t == 0) sh[0] = v;
    }
    __syncthreads();
    float r = sh[0];
    __syncthreads();
    return r;
}

// ---------------------------------------------------------------------------
// Utility kernels
// ---------------------------------------------------------------------------
__global__ void k_zero(float* p, int n) {
    int i = blockIdx.x * blockDim.x + threadIdx.x;
    if (i < n) p[i] = 0.f;
}

__global__ void k_round(const float* __restrict__ src, float* __restrict__ dst, int n4) {
    int i = blockIdx.x * blockDim.x + threadIdx.x;
    if (i < n4) {
        float4 v = ((const float4*)src)[i];
        uint4 u = make_uint4(f2tf32(v.x), f2tf32(v.y), f2tf32(v.z), f2tf32(v.w));
        ((uint4*)dst)[i] = u;
    }
}

__global__ void k_transpose(const float* __restrict__ src, float* __restrict__ dst) {
    __shared__ float tile[32][33];
    const int bx = blockIdx.x << 5, by = blockIdx.y << 5;
    #pragma unroll
    for (int j = 0; j < 4; j++)
        tile[threadIdx.y + j * 8][threadIdx.x] =
            src[(size_t)(by + threadIdx.y + j * 8) * 512 + bx + threadIdx.x];
    __syncthreads();
    #pragma unroll
    for (int j = 0; j < 4; j++)
        dst[(size_t)(bx + threadIdx.y + j * 8) * 512 + by + threadIdx.x] =
            tile[threadIdx.x][threadIdx.y + j * 8];
}

// BN + ELU, float4-vectorized. ROUND: store tf32-rounded (for GEMM consumers).
template<bool ROUND>
__global__ void __launch_bounds__(256) k_bn_elu(const float4* __restrict__ X,
                                                float4* __restrict__ Y,
                                                const float4* __restrict__ sum4,
                                                const float4* __restrict__ sumsq4,
                                                const float4* __restrict__ g4,
                                                const float4* __restrict__ bt4) {
    const float invN = 1.f / (float)RR;
    const int total4 = RR * Ee / 4;
    for (int i = blockIdx.x * blockDim.x + threadIdx.x; i < total4;
         i += gridDim.x * blockDim.x) {
        const int c4 = i & 127;
        float4 sm = sum4[c4], sq = sumsq4[c4], gg = g4[c4], bb = bt4[c4];
        float4 v = X[i];
        float m, va, sc, y;
        float4 o;
        m = sm.x * invN; va = sq.x * invN - m * m; sc = gg.x * rsqrtf(va + EPSV);
        y = (v.x - m) * sc + bb.x; o.x = y > 0.f ? y : expm1f(y);
        m = sm.y * invN; va = sq.y * invN - m * m; sc = gg.y * rsqrtf(va + EPSV);
        y = (v.y - m) * sc + bb.y; o.y = y > 0.f ? y : expm1f(y);
        m = sm.z * invN; va = sq.z * invN - m * m; sc = gg.z * rsqrtf(va + EPSV);
        y = (v.z - m) * sc + bb.z; o.z = y > 0.f ? y : expm1f(y);
        m = sm.w * invN; va = sq.w * invN - m * m; sc = gg.w * rsqrtf(va + EPSV);
        y = (v.w - m) * sc + bb.w; o.w = y > 0.f ? y : expm1f(y);
        if (ROUND) {
            uint4 u = make_uint4(f2tf32(o.x), f2tf32(o.y), f2tf32(o.z), f2tf32(o.w));
            ((uint4*)Y)[i] = u;
        } else {
            Y[i] = o;
        }
    }
}

// BN4 + softmax over q (contiguous rows of wT). One block per (b,k).
// Stores tf32-rounded (consumed by gemm_tn).
__global__ void k_bn_softmax(float* __restrict__ Wt,
                             const float* __restrict__ sum, const float* __restrict__ sumsq,
                             const float* __restrict__ g4, const float* __restrict__ b4) {
    const int bk = blockIdx.x;
    const int k = bk & 511;
    float* row = Wt + ((size_t)bk << 9);
    const float invN = 1.f / (float)RR;
    const float mean = sum[k] * invN;
    const float var = sumsq[k] * invN - mean * mean;
    const float sc = g4[k] * rsqrtf(var + EPSV);
    const float shf = b4[k] - mean * sc;
    const int t = threadIdx.x;
    float x0 = row[t] * sc + shf;
    float x1 = row[t + 256] * sc + shf;
    __shared__ float sh[32];
    float mx = blockReduceMax(fmaxf(x0, x1), sh);
    float e0 = expf(x0 - mx), e1 = expf(x1 - mx);
    float tot = blockReduceSum(e0 + e1, sh);
    float inv = 1.f / tot;
    ((uint32_t*)row)[t] = f2tf32(e0 * inv);
    ((uint32_t*)row)[t + 256] = f2tf32(e1 * inv);
}

// ---------------------------------------------------------------------------
// Tensor-core GEMMs: 128x128 C tile, BK=16, 256 threads (8 warps 4x2),
// warp tile 32x64, mma.m16n8k8.tf32, register-staged double-buffered smem,
// one __syncthreads per tile. Stats (sum/sumsq) fused into epilogues.
// ---------------------------------------------------------------------------

// GEMM1: C[RR,512] = unfold(m1) @ fr + kb   (A gathered raw, cvt at staging)
__global__ void __launch_bounds__(256, 2) k_gemm1(const float* __restrict__ Am1,
                                                  const float* __restrict__ Br,
                                                  const float* __restrict__ kb,
                                                  float* __restrict__ C,
                                                  float* __restrict__ ssum,
                                                  float* __restrict__ ssq) {
    __shared__ uint32_t As[2][16][PADW];
    __shared__ uint32_t Bs[2][16][PADW];
    float c[2][8][4] = {{{0.f}}};
    const int tid = threadIdx.x;
    const int lane = tid & 31, wid = tid >> 5;
    const int g = lane >> 2, t = lane & 3;
    const int wm = (wid & 3) << 5, wn = (wid >> 2) << 6;
    const int br = blockIdx.y << 7, bc = blockIdx.x << 7;
    const int lm = tid >> 2, lk4 = (tid & 3) << 2;
    const int lkb = tid >> 5, ln4 = (tid & 31) << 2;

    int bA[2], lA[2];
    #pragma unroll
    for (int rr = 0; rr < 2; rr++) {
        const int row = br + lm + (rr << 6);
        bA[rr] = row >> 9; lA[rr] = row & 511;
    }

    float4 av[2], bvv[2];
    #pragma unroll
    for (int rr = 0; rr < 2; rr++) {
        const int kg = lk4;
        const int sl = lA[rr] + (kg >> 9) - 2;
        av[rr] = make_float4(0.f, 0.f, 0.f, 0.f);
        if ((unsigned)sl < 512u)
            av[rr] = *(const float4*)(Am1 + ((size_t)((bA[rr] << 9) + sl) << 9) + (kg & 511));
        const int kk = lkb + (rr << 3);
        bvv[rr] = *(const float4*)(Br + (size_t)kk * Ee + bc + ln4);
    }
    #pragma unroll
    for (int rr = 0; rr < 2; rr++) {
        const int m = lm + (rr << 6);
        As[0][lk4 + 0][m] = f2tf32(av[rr].x);
        As[0][lk4 + 1][m] = f2tf32(av[rr].y);
        As[0][lk4 + 2][m] = f2tf32(av[rr].z);
        As[0][lk4 + 3][m] = f2tf32(av[rr].w);
        const int kk = lkb + (rr << 3);
        *(uint4*)&Bs[0][kk][ln4] = make_uint4(__float_as_uint(bvv[rr].x), __float_as_uint(bvv[rr].y),
                                              __float_as_uint(bvv[rr].z), __float_as_uint(bvv[rr].w));
    }

    const int nIter = KE / 16;
    for (int i = 0; i < nIter; i++) {
        const int buf = i & 1, nb = buf ^ 1;
        __syncthreads();
        const int k1 = (i + 1) << 4;
        if (i + 1 < nIter) {
            #pragma unroll
            for (int rr = 0; rr < 2; rr++) {
                const int kg = k1 + lk4;
                const int sl = lA[rr] + (kg >> 9) - 2;
                av[rr] = make_float4(0.f, 0.f, 0.f, 0.f);
                if ((unsigned)sl < 512u)
                    av[rr] = *(const float4*)(Am1 + ((size_t)((bA[rr] << 9) + sl) << 9) + (kg & 511));
                const int kk = lkb + (rr << 3);
                bvv[rr] = *(const float4*)(Br + (size_t)(k1 + kk) * Ee + bc + ln4);
            }
        }
        mma_core(As[buf], Bs[buf], c, g, t, wm, wn);
        if (i + 1 < nIter) {
            #pragma unroll
            for (int rr = 0; rr < 2; rr++) {
                const int m = lm + (rr << 6);
                As[nb][lk4 + 0][m] = f2tf32(av[rr].x);
                As[nb][lk4 + 1][m] = f2tf32(av[rr].y);
                As[nb][lk4 + 2][m] = f2tf32(av[rr].z);
                As[nb][lk4 + 3][m] = f2tf32(av[rr].w);
                const int kk = lkb + (rr << 3);
                *(uint4*)&Bs[nb][kk][ln4] = make_uint4(__float_as_uint(bvv[rr].x), __float_as_uint(bvv[rr].y),
                                                       __float_as_uint(bvv[rr].z), __float_as_uint(bvv[rr].w));
            }
        }
    }

    float cs[16] = {0.f}, cq[16] = {0.f};
    #pragma unroll
    for (int mt = 0; mt < 2; mt++)
        #pragma unroll
        for (int i = 0; i < 2; i++) {
            const int row = br + wm + mt * 16 + g + 8 * i;
            const int l = row & 511;
            #pragma unroll
            for (int nt = 0; nt < 8; nt++) {
                const int col = bc + wn + nt * 8 + 2 * t;
                float2 bv = *(const float2*)(kb + (size_t)l * 512 + col);
                float2 v;
                v.x = c[mt][nt][2 * i + 0] + bv.x;
                v.y = c[mt][nt][2 * i + 1] + bv.y;
                cs[nt * 2 + 0] += v.x; cq[nt * 2 + 0] += v.x * v.x;
                cs[nt * 2 + 1] += v.y; cq[nt * 2 + 1] += v.y * v.y;
                *(float2*)(C + (size_t)row * 512 + col) = v;
            }
        }
    colstats_epilogue(ssum, ssq, cs, cq, g, t, bc + wn);
}

// Fused NN GEMMs (z=0: q2 = l@wq + qb ; z=1: k2 = l@wk + kb), stats fused.
__global__ void __launch_bounds__(256, 2) k_gemm_nn(const float* __restrict__ A,
                                                    const float* __restrict__ Bq,
                                                    const float* __restrict__ Bk,
                                                    const float* __restrict__ biasq,
                                                    const float* __restrict__ biask,
                                                    float* __restrict__ Cq,
                                                    float* __restrict__ Ck,
                                                    float* __restrict__ stats) {
    const float* Bm = blockIdx.z ? Bk : Bq;
    const float* bias = blockIdx.z ? biask : biasq;
    float* C = blockIdx.z ? Ck : Cq;
    float* ssum = stats + (blockIdx.z ? 4 * Ee : 2 * Ee);
    float* ssq = ssum + Ee;
    __shared__ uint32_t As[2][16][PADW];
    __shared__ uint32_t Bs[2][16][PADW];
    float c[2][8][4] = {{{0.f}}};
    const int tid = threadIdx.x;
    const int lane = tid & 31, wid = tid >> 5;
    const int g = lane >> 2, t = lane & 3;
    const int wm = (wid & 3) << 5, wn = (wid >> 2) << 6;
    const int br = blockIdx.y << 7, bc = blockIdx.x << 7;
    const int lm = tid >> 2, lk4 = (tid & 3) << 2;
    const int lkb = tid >> 5, ln4 = (tid & 31) << 2;

    float4 av[2], bvv[2];
    #pragma unroll
    for (int rr = 0; rr < 2; rr++) {
        av[rr] = *(const float4*)(A + (size_t)(br + lm + (rr << 6)) * 512 + lk4);
        const int kk = lkb + (rr << 3);
        bvv[rr] = *(const float4*)(Bm + (size_t)kk * 512 + bc + ln4);
    }
    #pragma unroll
    for (int rr = 0; rr < 2; rr++) {
        const int m = lm + (rr << 6);
        As[0][lk4 + 0][m] = __float_as_uint(av[rr].x);
        As[0][lk4 + 1][m] = __float_as_uint(av[rr].y);
        As[0][lk4 + 2][m] = __float_as_uint(av[rr].z);
        As[0][lk4 + 3][m] = __float_as_uint(av[rr].w);
        const int kk = lkb + (rr << 3);
        *(uint4*)&Bs[0][kk][ln4] = make_uint4(__float_as_uint(bvv[rr].x), __float_as_uint(bvv[rr].y),
                                              __float_as_uint(bvv[rr].z), __float_as_uint(bvv[rr].w));
    }

    const int nIter = 32;
    for (int i = 0; i < nIter; i++) {
        const int buf = i & 1, nb = buf ^ 1;
        __syncthreads();
        const int k1 = (i + 1) << 4;
        if (i + 1 < nIter) {
            #pragma unroll
            for (int rr = 0; rr < 2; rr++) {
                av[rr] = *(const float4*)(A + (size_t)(br + lm + (rr << 6)) * 512 + k1 + lk4);
                const int kk = lkb + (rr << 3);
                bvv[rr] = *(const float4*)(Bm + (size_t)(k1 + kk) * 512 + bc + ln4);
            }
        }
        mma_core(As[buf], Bs[buf], c, g, t, wm, wn);
        if (i + 1 < nIter) {
            #pragma unroll
            for (int rr = 0; rr < 2; rr++) {
                const int m = lm + (rr << 6);
                As[nb][lk4 + 0][m] = __float_as_uint(av[rr].x);
                As[nb][lk4 + 1][m] = __float_as_uint(av[rr].y);
                As[nb][lk4 + 2][m] = __float_as_uint(av[rr].z);
                As[nb][lk4 + 3][m] = __float_as_uint(av[rr].w);
                const int kk = lkb + (rr << 3);
                *(uint4*)&Bs[nb][kk][ln4] = make_uint4(__float_as_uint(bvv[rr].x), __float_as_uint(bvv[rr].y),
                                                       __float_as_uint(bvv[rr].z), __float_as_uint(bvv[rr].w));
            }
        }
    }

    float cs[16] = {0.f}, cq[16] = {0.f};
    #pragma unroll
    for (int mt = 0; mt < 2; mt++)
        #pragma unroll
        for (int i = 0; i < 2; i++) {
            const int row = br + wm + mt * 16 + g + 8 * i;
            const int l = row & 511;
            #pragma unroll
            for (int nt = 0; nt < 8; nt++) {
                const int col = bc + wn + nt * 8 + 2 * t;
                float2 bv = *(const float2*)(bias + (size_t)l * 512 + col);
                float2 v;
                v.x = c[mt][nt][2 * i + 0] + bv.x;
                v.y = c[mt][nt][2 * i + 1] + bv.y;
                cs[nt * 2 + 0] += v.x; cq[nt * 2 + 0] += v.x * v.x;
                cs[nt * 2 + 1] += v.y; cq[nt * 2 + 1] += v.y * v.y;
                *(float2*)(C + (size_t)row * 512 + col) = v;
            }
        }
    colstats_epilogue(ssum, ssq, cs, cq, g, t, bc + wn);
}

// Batched NT GEMM: per batch z, C[k,q] = sum_e k2[k,e]*q2[q,e] + wbT[k,q]
// Row (=k) stats fused for BN4.
__global__ void __launch_bounds__(256, 2) k_gemm_nt(const float* __restrict__ Ain,
                                                    const float* __restrict__ Bin,
                                                    const float* __restrict__ wbT,
                                                    float* __restrict__ Cout,
                                                    float* __restrict__ rsum,
                                                    float* __restrict__ rsq) {
    const int bz = blockIdx.z;
    const float* A = Ain + (size_t)bz * Ll * Ee;
    const float* Bm = Bin + (size_t)bz * Ll * Ee;
    float* C = Cout + (size_t)bz * Ll * Ll;
    __shared__ uint32_t As[2][16][PADW];
    __shared__ uint32_t Bs[2][16][PADW];
    float c[2][8][4] = {{{0.f}}};
    const int tid = threadIdx.x;
    const int lane = tid & 31, wid = tid >> 5;
    const int g = lane >> 2, t = lane & 3;
    const int wm = (wid & 3) << 5, wn = (wid >> 2) << 6;
    const int br = blockIdx.y << 7, bc = blockIdx.x << 7;
    const int lm = tid >> 2, lk4 = (tid & 3) << 2;

    float4 av[2], bv[2];
    #pragma unroll
    for (int rr = 0; rr < 2; rr++) {
        const int m = lm + (rr << 6);
        av[rr] = *(const float4*)(A + (size_t)(br + m) * 512 + lk4);
        bv[rr] = *(const float4*)(Bm + (size_t)(bc + m) * 512 + lk4);
    }
    #pragma unroll
    for (int rr = 0; rr < 2; rr++) {
        const int m = lm + (rr << 6);
        As[0][lk4 + 0][m] = __float_as_uint(av[rr].x);
        As[0][lk4 + 1][m] = __float_as_uint(av[rr].y);
        As[0][lk4 + 2][m] = __float_as_uint(av[rr].z);
        As[0][lk4 + 3][m] = __float_as_uint(av[rr].w);
        Bs[0][lk4 + 0][m] = __float_as_uint(bv[rr].x);
        Bs[0][lk4 + 1][m] = __float_as_uint(bv[rr].y);
        Bs[0][lk4 + 2][m] = __float_as_uint(bv[rr].z);
        Bs[0][lk4 + 3][m] = __float_as_uint(bv[rr].w);
    }

    const int nIter = 32;
    for (int i = 0; i < nIter; i++) {
        const int buf = i & 1, nb = buf ^ 1;
        __syncthreads();
        const int k1 = (i + 1) << 4;
        if (i + 1 < nIter) {
            #pragma unroll
            for (int rr = 0; rr < 2; rr++) {
                const int m = lm + (rr << 6);
                av[rr] = *(const float4*)(A + (size_t)(br + m) * 512 + k1 + lk4);
                bv[rr] = *(const float4*)(Bm + (size_t)(bc + m) * 512 + k1 + lk4);
            }
        }
        mma_core(As[buf], Bs[buf], c, g, t, wm, wn);
        if (i + 1 < nIter) {
            #pragma unroll
            for (int rr = 0; rr < 2; rr++) {
                const int m = lm + (rr << 6);
                As[nb][lk4 + 0][m] = __float_as_uint(av[rr].x);
                As[nb][lk4 + 1][m] = __float_as_uint(av[rr].y);
                As[nb][lk4 + 2][m] = __float_as_uint(av[rr].z);
                As[nb][lk4 + 3][m] = __float_as_uint(av[rr].w);
                Bs[nb][lk4 + 0][m] = __float_as_uint(bv[rr].x);
                Bs[nb][lk4 + 1][m] = __float_as_uint(bv[rr].y);
                Bs[nb][lk4 + 2][m] = __float_as_uint(bv[rr].z);
                Bs[nb][lk4 + 3][m] = __float_as_uint(bv[rr].w);
            }
        }
    }

    float rs[4] = {0.f}, rq[4] = {0.f};
    #pragma unroll
    for (int mt = 0; mt < 2; mt++)
        #pragma unroll
        for (int i = 0; i < 2; i++) {
            const int row = br + wm + mt * 16 + g + 8 * i;   // k
            #pragma unroll
            for (int nt = 0; nt < 8; nt++) {
                const int col = bc + wn + nt * 8 + 2 * t;    // q
                float2 bv2 = *(const float2*)(wbT + (size_t)row * 512 + col);
                float2 v;
                v.x = c[mt][nt][2 * i + 0] + bv2.x;
                v.y = c[mt][nt][2 * i + 1] + bv2.y;
                rs[mt * 2 + i] += v.x + v.y;
                rq[mt * 2 + i] += v.x * v.x + v.y * v.y;
                *(float2*)(C + (size_t)row * 512 + col) = v;
            }
        }
    // reduce over t lanes (warp covers 64 cols of each row); lane t==0 commits.
    #pragma unroll
    for (int x = 0; x < 4; x++) {
        float s = rs[x], q = rq[x];
        s += __shfl_xor_sync(0xffffffffu, s, 1); q += __shfl_xor_sync(0xffffffffu, q, 1);
        s += __shfl_xor_sync(0xffffffffu, s, 2); q += __shfl_xor_sync(0xffffffffu, q, 2);
        if (t == 0) {
            const int row = br + wm + (x >> 1) * 16 + g + 8 * (x & 1);
            atomicAdd(&rsum[row], s);
            atomicAdd(&rsq[row], q);
        }
    }
}

// Batched TN GEMM: per batch z, C[q,e] = sum_k wT[k,q]*l[k,e]; col stats fused.
__global__ void __launch_bounds__(256, 2) k_gemm_tn(const float* __restrict__ Ain,
                                                    const float* __restrict__ Bin,
                                                    float* __restrict__ Cout,
                                                    float* __restrict__ ssum,
                                                    float* __restrict__ ssq) {
    const int bz = blockIdx.z;
    const float* A = Ain + (size_t)bz * Ll * Ll;
    const float* Bm = Bin + (size_t)bz * Ll * Ee;
    float* C = Cout + (size_t)bz * Ll * Ee;
    __shared__ uint32_t As[2][16][PADW];
    __shared__ uint32_t Bs[2][16][PADW];
    float c[2][8][4] = {{{0.f}}};
    const int tid = threadIdx.x;
    const int lane = tid & 31, wid = tid >> 5;
    const int g = lane >> 2, t = lane & 3;
    const int wm = (wid & 3) << 5, wn = (wid >> 2) << 6;
    const int br = blockIdx.y << 7, bc = blockIdx.x << 7;
    const int lkb = tid >> 5, ln4 = (tid & 31) << 2;

    float4 av[2], bv[2];
    #pragma unroll
    for (int rr = 0; rr < 2; rr++) {
        const int kk = lkb + (rr << 3);
        av[rr] = *(const float4*)(A + (size_t)kk * 512 + br + ln4);
        bv[rr] = *(const float4*)(Bm + (size_t)kk * 512 + bc + ln4);
    }
    #pragma unroll
    for (int rr = 0; rr < 2; rr++) {
        const int kk = lkb + (rr << 3);
        *(uint4*)&As[0][kk][ln4] = make_uint4(__float_as_uint(av[rr].x), __float_as_uint(av[rr].y),
                                              __float_as_uint(av[rr].z), __float_as_uint(av[rr].w));
        *(uint4*)&Bs[0][kk][ln4] = make_uint4(__float_as_uint(bv[rr].x), __float_as_uint(bv[rr].y),
                                              __float_as_uint(bv[rr].z), __float_as_uint(bv[rr].w));
    }

    const int nIter = 32;
    for (int i = 0; i < nIter; i++) {
        const int buf = i & 1, nb = buf ^ 1;
        __syncthreads();
        const int k1 = (i + 1) << 4;
        if (i + 1 < nIter) {
            #pragma unroll
            for (int rr = 0; rr < 2; rr++) {
                const int kk = lkb + (rr << 3);
                av[rr] = *(const float4*)(A + (size_t)(k1 + kk) * 512 + br + ln4);
                bv[rr] = *(const float4*)(Bm + (size_t)(k1 + kk) * 512 + bc + ln4);
            }
        }
        mma_core(As[buf], Bs[buf], c, g, t, wm, wn);
        if (i + 1 < nIter) {
            #pragma unroll
            for (int rr = 0; rr < 2; rr++) {
                const int kk = lkb + (rr << 3);
                *(uint4*)&As[nb][kk][ln4] = make_uint4(__float_as_uint(av[rr].x), __float_as_uint(av[rr].y),
                                                       __float_as_uint(av[rr].z), __float_as_uint(av[rr].w));
                *(uint4*)&Bs[nb][kk][ln4] = make_uint4(__float_as_uint(bv[rr].x), __float_as_uint(bv[rr].y),
                                                       __float_as_uint(bv[rr].z), __float_as_uint(bv[rr].w));
            }
        }
    }

    float cs[16] = {0.f}, cq[16] = {0.f};
    #pragma unroll
    for (int mt = 0; mt < 2; mt++)
        #pragma unroll
        for (int i = 0; i < 2; i++) {
            const int row = br + wm + mt * 16 + g + 8 * i;
            #pragma unroll
            for (int nt = 0; nt < 8; nt++) {
                const int col = bc + wn + nt * 8 + 2 * t;
                float2 v;
                v.x = c[mt][nt][2 * i + 0];
                v.y = c[mt][nt][2 * i + 1];
                cs[nt * 2 + 0] += v.x; cq[nt * 2 + 0] += v.x * v.x;
                cs[nt * 2 + 1] += v.y; cq[nt * 2 + 1] += v.y * v.y;
                *(float2*)(C + (size_t)row * 512 + col) = v;
            }
        }
    colstats_epilogue(ssum, ssq, cs, cq, g, t, bc + wn);
}

// ---------------------------------------------------------------------------
// Launcher
// ---------------------------------------------------------------------------
extern "C" void kernel_launch(void* const* d_in, const int* in_sizes, int n_in,
                              void* d_out, int out_size) {
    const float* m1 = (const float*)d_in[0];
    const float* f  = (const float*)d_in[1];
    const float* wq = (const float*)d_in[2];
    const float* wk = (const float*)d_in[3];
    const float* qb = (const float*)d_in[4];
    const float* kb = (const float*)d_in[5];
    const float* wb = (const float*)d_in[6];
    const float* g1 = (const float*)d_in[7];  const float* b1 = (const float*)d_in[8];
    const float* g2 = (const float*)d_in[9];  const float* b2 = (const float*)d_in[10];
    const float* g3 = (const float*)d_in[11]; const float* b3 = (const float*)d_in[12];
    const float* g4 = (const float*)d_in[13]; const float* b4 = (const float*)d_in[14];
    const float* g5 = (const float*)d_in[15]; const float* b5 = (const float*)d_in[16];

    float *pl, *pq, *pk, *pw, *po, *ps, *pwbT, *pfr, *pwqr, *pwkr;
    cudaGetSymbolAddress((void**)&pl, g_l);
    cudaGetSymbolAddress((void**)&pq, g_q);
    cudaGetSymbolAddress((void**)&pk, g_k);
    cudaGetSymbolAddress((void**)&pw, g_w);
    cudaGetSymbolAddress((void**)&po, g_o);
    cudaGetSymbolAddress((void**)&ps, g_s);
    cudaGetSymbolAddress((void**)&pwbT, g_wbT);
    cudaGetSymbolAddress((void**)&pfr, g_fr);
    cudaGetSymbolAddress((void**)&pwqr, g_wqr);
    cudaGetSymbolAddress((void**)&pwkr, g_wkr);

    const int T = 256;

    // pre-passes
    k_zero<<<20, T>>>(ps, 10 * Ee);
    k_transpose<<<dim3(16, 16), dim3(32, 8)>>>(wb, pwbT);
    k_round<<<1280, T>>>(f, pfr, KE * Ee / 4);
    k_round<<<256, T>>>(wq, pwqr, Ee * Ee / 4);
    k_round<<<256, T>>>(wk, pwkr, Ee * Ee / 4);

    // 1) l_pre = unfold(m1) @ f + kb (stats fused) ; BN1 + ELU (rounded store)
    k_gemm1<<<dim3(4, 128), T>>>(m1, pfr, kb, pl, ps + 0 * Ee, ps + 1 * Ee);
    k_bn_elu<true><<<2048, T>>>((const float4*)pl, (float4*)pl,
                                (const float4*)(ps + 0 * Ee), (const float4*)(ps + 1 * Ee),
                                (const float4*)g1, (const float4*)b1);

    // 2) q2 / k2 (fused launch, stats fused)
    k_gemm_nn<<<dim3(4, 128, 2), T>>>(pl, pwqr, pwkr, qb, kb, pq, pk, ps);
    k_bn_elu<true><<<2048, T>>>((const float4*)pq, (float4*)pq,
                                (const float4*)(ps + 2 * Ee), (const float4*)(ps + 3 * Ee),
                                (const float4*)g2, (const float4*)b2);
    k_bn_elu<true><<<2048, T>>>((const float4*)pk, (float4*)pk,
                                (const float4*)(ps + 4 * Ee), (const float4*)(ps + 5 * Ee),
                                (const float4*)g3, (const float4*)b3);

    // 3) wT[b,k,q] = k2 @ q2^T + wbT (row stats fused) ; BN4 + softmax over q
    k_gemm_nt<<<dim3(4, 4, 32), T>>>(pk, pq, pwbT, pw, ps + 8 * Ee, ps + 9 * Ee);
    k_bn_softmax<<<16384, T>>>(pw, ps + 8 * Ee, ps + 9 * Ee, g4, b4);

    // 4) out_pre = wT^T @ l (col stats fused) ; BN5 + ELU -> d_out
    k_gemm_tn<<<dim3(4, 4, 32), T>>>(pw, pl, po, ps + 6 * Ee, ps + 7 * Ee);
    k_bn_elu<false><<<2048, T>>>((const float4*)po, (float4*)d_out,
                                 (const float4*)(ps + 6 * Ee), (const float4*)(ps + 7 * Ee),
                                 (const float4*)g5, (const float4*)b5);
}

// round 8
// speedup vs baseline: 2.7748x; 1.0613x over previous
#include <cuda_runtime.h>
#include <math.h>
#include <stdint.h>

#define Bb 32
#define Ll 512
#define Ee 512
#define RR (Bb*Ll)
#define KE (5*Ee)
#define EPSV 1e-3f
#define PADW 136

__device__ float g_l[RR*Ee];
__device__ float g_q[RR*Ee];
__device__ float g_k[RR*Ee];
__device__ float g_w[Bb*Ll*Ll];     // wT[b,k,q]
__device__ float g_o[RR*Ee];
__device__ float g_fr[KE*Ee];
__device__ float g_wqr[Ee*Ee];
__device__ float g_wkr[Ee*Ee];
__device__ float g_wbT[Ll*Ll];
__device__ float g_s[10*Ee];

__device__ __forceinline__ uint32_t f2tf32(float x) {
    uint32_t r;
    asm("cvt.rna.tf32.f32 %0, %1;" : "=r"(r) : "f"(x));
    return r;
}

// 64x64 warp tile mma core over swizzled [16][PADW] tiles.
// Swizzle: element (k, col) lives at [k][col ^ (((k>>2)&3)<<3)].
__device__ __forceinline__ void mma_core64(const uint32_t (*As)[PADW],
                                           const uint32_t (*Bs)[PADW],
                                           float c[4][8][4],
                                           int g, int t, int wm, int wn) {
    #pragma unroll
    for (int ks = 0; ks < 2; ks++) {
        const int kb = ks * 8;
        const int s0 = ks * 16, s1 = ks * 16 + 8;
        uint32_t a[4][4], b[8][2];
        #pragma unroll
        for (int mt = 0; mt < 4; mt++) {
            const int m = wm + mt * 16 + g;
            a[mt][0] = As[kb + t][m ^ s0];
            a[mt][1] = As[kb + t][(m + 8) ^ s0];
            a[mt][2] = As[kb + t + 4][m ^ s1];
            a[mt][3] = As[kb + t + 4][(m + 8) ^ s1];
        }
        #pragma unroll
        for (int nt = 0; nt < 8; nt++) {
            const int n = wn + nt * 8 + g;
            b[nt][0] = Bs[kb + t][n ^ s0];
            b[nt][1] = Bs[kb + t + 4][n ^ s1];
        }
        #pragma unroll
        for (int mt = 0; mt < 4; mt++)
            #pragma unroll
            for (int nt = 0; nt < 8; nt++)
                asm volatile(
                    "mma.sync.aligned.m16n8k8.row.col.f32.tf32.tf32.f32 "
                    "{%0,%1,%2,%3},{%4,%5,%6,%7},{%8,%9},{%0,%1,%2,%3};"
                    : "+f"(c[mt][nt][0]), "+f"(c[mt][nt][1]),
                      "+f"(c[mt][nt][2]), "+f"(c[mt][nt][3])
                    : "r"(a[mt][0]), "r"(a[mt][1]), "r"(a[mt][2]), "r"(a[mt][3]),
                      "r"(b[nt][0]), "r"(b[nt][1]));
    }
}

// m-major staging store: 4 k-contig words at column m, rows lk4..lk4+3.
// sw = (tid&3)<<3 makes these STS.32 conflict-free.
__device__ __forceinline__ void stA(uint32_t (*S)[PADW], int lk4, int m, int sw,
                                    float4 v) {
    const int mc = m ^ sw;
    S[lk4 + 0][mc] = __float_as_uint(v.x);
    S[lk4 + 1][mc] = __float_as_uint(v.y);
    S[lk4 + 2][mc] = __float_as_uint(v.z);
    S[lk4 + 3][mc] = __float_as_uint(v.w);
}
__device__ __forceinline__ void stA_cvt(uint32_t (*S)[PADW], int lk4, int m, int sw,
                                        float4 v) {
    const int mc = m ^ sw;
    S[lk4 + 0][mc] = f2tf32(v.x);
    S[lk4 + 1][mc] = f2tf32(v.y);
    S[lk4 + 2][mc] = f2tf32(v.z);
    S[lk4 + 3][mc] = f2tf32(v.w);
}
// k-major staging store: one uint4 row chunk at row kk, cols ln4..+3.
__device__ __forceinline__ void stB(uint32_t (*S)[PADW], int kk, int ln4, float4 v) {
    const int c = ln4 ^ (((kk >> 2) & 3) << 3);
    *(uint4*)&S[kk][c] = make_uint4(__float_as_uint(v.x), __float_as_uint(v.y),
                                    __float_as_uint(v.z), __float_as_uint(v.w));
}

__device__ __forceinline__ void colstats_epilogue(float* __restrict__ sum,
                                                  float* __restrict__ sumsq,
                                                  const float cs[16], const float cq[16],
                                                  int g, int t, int bcwn) {
    #pragma unroll
    for (int x = 0; x < 16; x++) {
        float s = cs[x], q = cq[x];
        s += __shfl_xor_sync(0xffffffffu, s, 4);  q += __shfl_xor_sync(0xffffffffu, q, 4);
        s += __shfl_xor_sync(0xffffffffu, s, 8);  q += __shfl_xor_sync(0xffffffffu, q, 8);
        s += __shfl_xor_sync(0xffffffffu, s, 16); q += __shfl_xor_sync(0xffffffffu, q, 16);
        if (g == 0) {
            const int col = bcwn + (x >> 1) * 8 + 2 * t + (x & 1);
            atomicAdd(&sum[col], s);
            atomicAdd(&sumsq[col], q);
        }
    }
}

__device__ __forceinline__ float blockReduceSum(float v, float* sh) {
    const int t = threadIdx.x;
    #pragma unroll
    for (int o = 16; o > 0; o >>= 1) v += __shfl_xor_sync(0xffffffffu, v, o);
    if ((t & 31) == 0) sh[t >> 5] = v;
    __syncthreads();
    if (t < 32) {
        v = (t < (int)(blockDim.x >> 5)) ? sh[t] : 0.f;
        #pragma unroll
        for (int o = 16; o > 0; o >>= 1) v += __shfl_xor_sync(0xffffffffu, v, o);
        if (t == 0) sh[0] = v;
    }
    __syncthreads();
    float r = sh[0];
    __syncthreads();
    return r;
}

__device__ __forceinline__ float blockReduceMax(float v, float* sh) {
    const int t = threadIdx.x;
    #pragma unroll
    for (int o = 16; o > 0; o >>= 1) v = fmaxf(v, __shfl_xor_sync(0xffffffffu, v, o));
    if ((t & 31) == 0) sh[t >> 5] = v;
    __syncthreads();
    if (t < 32) {
        v = (t < (int)(blockDim.x >> 5)) ? sh[t] : -INFINITY;
        #pragma unroll
        for (int o = 16; o > 0; o >>= 1) v = fmaxf(v, __shfl_xor_sync(0xffffffffu, v, o));
        if (t == 0) sh[0] = v;
    }
    __syncthreads();
    float r = sh[0];
    __syncthreads();
    return r;
}

__global__ void k_zero(float* p, int n) {
    int i = blockIdx.x * blockDim.x + threadIdx.x;
    if (i < n) p[i] = 0.f;
}

__global__ void k_round(const float* __restrict__ src, float* __restrict__ dst, int n4) {
    int i = blockIdx.x * blockDim.x + threadIdx.x;
    if (i < n4) {
        float4 v = ((const float4*)src)[i];
        ((uint4*)dst)[i] = make_uint4(f2tf32(v.x), f2tf32(v.y), f2tf32(v.z), f2tf32(v.w));
    }
}

__global__ void k_transpose(const float* __restrict__ src, float* __restrict__ dst) {
    __shared__ float tile[32][33];
    const int bx = blockIdx.x << 5, by = blockIdx.y << 5;
    #pragma unroll
    for (int j = 0; j < 4; j++)
        tile[threadIdx.y + j * 8][threadIdx.x] =
            src[(size_t)(by + threadIdx.y + j * 8) * 512 + bx + threadIdx.x];
    __syncthreads();
    #pragma unroll
    for (int j = 0; j < 4; j++)
        dst[(size_t)(bx + threadIdx.y + j * 8) * 512 + by + threadIdx.x] =
            tile[threadIdx.x][threadIdx.y + j * 8];
}

template<bool ROUND>
__global__ void __launch_bounds__(256) k_bn_elu(const float4* __restrict__ X,
                                                float4* __restrict__ Y,
                                                const float4* __restrict__ sum4,
                                                const float4* __restrict__ sumsq4,
                                                const float4* __restrict__ g4,
                                                const float4* __restrict__ bt4) {
    const float invN = 1.f / (float)RR;
    const int total4 = RR * Ee / 4;
    for (int i = blockIdx.x * blockDim.x + threadIdx.x; i < total4;
         i += gridDim.x * blockDim.x) {
        const int c4 = i & 127;
        float4 sm = sum4[c4], sq = sumsq4[c4], gg = g4[c4], bb = bt4[c4];
        float4 v = X[i];
        float m, va, sc, y;
        float4 o;
        m = sm.x * invN; va = sq.x * invN - m * m; sc = gg.x * rsqrtf(va + EPSV);
        y = (v.x - m) * sc + bb.x; o.x = y > 0.f ? y : expm1f(y);
        m = sm.y * invN; va = sq.y * invN - m * m; sc = gg.y * rsqrtf(va + EPSV);
        y = (v.y - m) * sc + bb.y; o.y = y > 0.f ? y : expm1f(y);
        m = sm.z * invN; va = sq.z * invN - m * m; sc = gg.z * rsqrtf(va + EPSV);
        y = (v.z - m) * sc + bb.z; o.z = y > 0.f ? y : expm1f(y);
        m = sm.w * invN; va = sq.w * invN - m * m; sc = gg.w * rsqrtf(va + EPSV);
        y = (v.w - m) * sc + bb.w; o.w = y > 0.f ? y : expm1f(y);
        if (ROUND)
            ((uint4*)Y)[i] = make_uint4(f2tf32(o.x), f2tf32(o.y), f2tf32(o.z), f2tf32(o.w));
        else
            Y[i] = o;
    }
}

__global__ void k_bn_softmax(float* __restrict__ Wt,
                             const float* __restrict__ sum, const float* __restrict__ sumsq,
                             const float* __restrict__ g4, const float* __restrict__ b4) {
    const int bk = blockIdx.x;
    const int k = bk & 511;
    float* row = Wt + ((size_t)bk << 9);
    const float invN = 1.f / (float)RR;
    const float mean = sum[k] * invN;
    const float var = sumsq[k] * invN - mean * mean;
    const float sc = g4[k] * rsqrtf(var + EPSV);
    const float shf = b4[k] - mean * sc;
    const int t = threadIdx.x;
    float x0 = row[t] * sc + shf;
    float x1 = row[t + 256] * sc + shf;
    __shared__ float sh[32];
    float mx = blockReduceMax(fmaxf(x0, x1), sh);
    float e0 = expf(x0 - mx), e1 = expf(x1 - mx);
    float tot = blockReduceSum(e0 + e1, sh);
    float inv = 1.f / tot;
    ((uint32_t*)row)[t] = f2tf32(e0 * inv);
    ((uint32_t*)row)[t + 256] = f2tf32(e1 * inv);
}

// ---------------------------------------------------------------------------
// GEMMs: 128x128 C tile, BK=16, 128 threads (4 warps 2x2), warp tile 64x64.
// Register double-buffered smem, swizzled stores, one sync/iter, stats fused.
// ---------------------------------------------------------------------------

// GEMM1: C = unfold(m1) @ fr + kb. A gathered m-major (cvt at staging), B k-major.
__global__ void __launch_bounds__(128) k_gemm1(const float* __restrict__ Am1,
                                               const float* __restrict__ Br,
                                               const float* __restrict__ kb,
                                               float* __restrict__ C,
                                               float* __restrict__ ssum,
                                               float* __restrict__ ssq) {
    __shared__ uint32_t As[2][16][PADW];
    __shared__ uint32_t Bs[2][16][PADW];
    float c[4][8][4] = {{{0.f}}};
    const int tid = threadIdx.x;
    const int lane = tid & 31, wid = tid >> 5;
    const int g = lane >> 2, t = lane & 3;
    const int wm = (wid & 1) << 6, wn = (wid >> 1) << 6;
    const int br = blockIdx.y << 7, bc = blockIdx.x << 7;
    const int lm = tid >> 2, lk4 = (tid & 3) << 2, sw = (tid & 3) << 3;
    const int lkb = tid >> 5, ln4 = lane << 2;

    int bA[4], lA[4];
    #pragma unroll
    for (int rr = 0; rr < 4; rr++) {
        const int row = br + lm + (rr << 5);
        bA[rr] = row >> 9; lA[rr] = row & 511;
    }

    float4 av[4], bv[4];
    #pragma unroll
    for (int rr = 0; rr < 4; rr++) {
        const int sl = lA[rr] - 2;   // window 0 at k0=0
        av[rr] = make_float4(0.f, 0.f, 0.f, 0.f);
        if ((unsigned)sl < 512u)
            av[rr] = *(const float4*)(Am1 + ((size_t)((bA[rr] << 9) + sl) << 9) + lk4);
        bv[rr] = *(const float4*)(Br + (size_t)(lkb + (rr << 2)) * Ee + bc + ln4);
    }
    #pragma unroll
    for (int rr = 0; rr < 4; rr++) {
        stA_cvt(As[0], lk4, lm + (rr << 5), sw, av[rr]);
        stB(Bs[0], lkb + (rr << 2), ln4, bv[rr]);
    }

    const int nIter = KE / 16;
    for (int i = 0; i < nIter; i++) {
        const int buf = i & 1, nb = buf ^ 1;
        __syncthreads();
        const int k1 = (i + 1) << 4;
        if (i + 1 < nIter) {
            const int win = k1 >> 9, kc = k1 & 511;
            #pragma unroll
            for (int rr = 0; rr < 4; rr++) {
                const int sl = lA[rr] + win - 2;
                av[rr] = make_float4(0.f, 0.f, 0.f, 0.f);
                if ((unsigned)sl < 512u)
                    av[rr] = *(const float4*)(Am1 + ((size_t)((bA[rr] << 9) + sl) << 9) + kc + lk4);
                bv[rr] = *(const float4*)(Br + (size_t)(k1 + lkb + (rr << 2)) * Ee + bc + ln4);
            }
        }
        mma_core64(As[buf], Bs[buf], c, g, t, wm, wn);
        if (i + 1 < nIter) {
            #pragma unroll
            for (int rr = 0; rr < 4; rr++) {
                stA_cvt(As[nb], lk4, lm + (rr << 5), sw, av[rr]);
                stB(Bs[nb], lkb + (rr << 2), ln4, bv[rr]);
            }
        }
    }

    float cs[16] = {0.f}, cq[16] = {0.f};
    #pragma unroll
    for (int mt = 0; mt < 4; mt++)
        #pragma unroll
        for (int i = 0; i < 2; i++) {
            const int row = br + wm + mt * 16 + g + 8 * i;
            const int l = row & 511;
            #pragma unroll
            for (int nt = 0; nt < 8; nt++) {
                const int col = bc + wn + nt * 8 + 2 * t;
                float2 bvv = *(const float2*)(kb + (size_t)l * 512 + col);
                float2 v;
                v.x = c[mt][nt][2 * i + 0] + bvv.x;
                v.y = c[mt][nt][2 * i + 1] + bvv.y;
                cs[nt * 2 + 0] += v.x; cq[nt * 2 + 0] += v.x * v.x;
                cs[nt * 2 + 1] += v.y; cq[nt * 2 + 1] += v.y * v.y;
                *(float2*)(C + (size_t)row * 512 + col) = v;
            }
        }
    colstats_epilogue(ssum, ssq, cs, cq, g, t, bc + wn);
}

// Fused NN GEMMs (z=0: q2 = l@wq + qb ; z=1: k2 = l@wk + kb), stats fused.
__global__ void __launch_bounds__(128) k_gemm_nn(const float* __restrict__ A,
                                                 const float* __restrict__ Bq,
                                                 const float* __restrict__ Bk,
                                                 const float* __restrict__ biasq,
                                                 const float* __restrict__ biask,
                                                 float* __restrict__ Cq,
                                                 float* __restrict__ Ck,
                                                 float* __restrict__ stats) {
    const float* Bm = blockIdx.z ? Bk : Bq;
    const float* bias = blockIdx.z ? biask : biasq;
    float* C = blockIdx.z ? Ck : Cq;
    float* ssum = stats + (blockIdx.z ? 4 * Ee : 2 * Ee);
    float* ssq = ssum + Ee;
    __shared__ uint32_t As[2][16][PADW];
    __shared__ uint32_t Bs[2][16][PADW];
    float c[4][8][4] = {{{0.f}}};
    const int tid = threadIdx.x;
    const int lane = tid & 31, wid = tid >> 5;
    const int g = lane >> 2, t = lane & 3;
    const int wm = (wid & 1) << 6, wn = (wid >> 1) << 6;
    const int br = blockIdx.y << 7, bc = blockIdx.x << 7;
    const int lm = tid >> 2, lk4 = (tid & 3) << 2, sw = (tid & 3) << 3;
    const int lkb = tid >> 5, ln4 = lane << 2;

    float4 av[4], bv[4];
    #pragma unroll
    for (int rr = 0; rr < 4; rr++) {
        av[rr] = *(const float4*)(A + (size_t)(br + lm + (rr << 5)) * 512 + lk4);
        bv[rr] = *(const float4*)(Bm + (size_t)(lkb + (rr << 2)) * 512 + bc + ln4);
    }
    #pragma unroll
    for (int rr = 0; rr < 4; rr++) {
        stA(As[0], lk4, lm + (rr << 5), sw, av[rr]);
        stB(Bs[0], lkb + (rr << 2), ln4, bv[rr]);
    }

    const int nIter = 32;
    for (int i = 0; i < nIter; i++) {
        const int buf = i & 1, nb = buf ^ 1;
        __syncthreads();
        const int k1 = (i + 1) << 4;
        if (i + 1 < nIter) {
            #pragma unroll
            for (int rr = 0; rr < 4; rr++) {
                av[rr] = *(const float4*)(A + (size_t)(br + lm + (rr << 5)) * 512 + k1 + lk4);
                bv[rr] = *(const float4*)(Bm + (size_t)(k1 + lkb + (rr << 2)) * 512 + bc + ln4);
            }
        }
        mma_core64(As[buf], Bs[buf], c, g, t, wm, wn);
        if (i + 1 < nIter) {
            #pragma unroll
            for (int rr = 0; rr < 4; rr++) {
                stA(As[nb], lk4, lm + (rr << 5), sw, av[rr]);
                stB(Bs[nb], lkb + (rr << 2), ln4, bv[rr]);
            }
        }
    }

    float cs[16] = {0.f}, cq[16] = {0.f};
    #pragma unroll
    for (int mt = 0; mt < 4; mt++)
        #pragma unroll
        for (int i = 0; i < 2; i++) {
            const int row = br + wm + mt * 16 + g + 8 * i;
            const int l = row & 511;
            #pragma unroll
            for (int nt = 0; nt < 8; nt++) {
                const int col = bc + wn + nt * 8 + 2 * t;
                float2 bvv = *(const float2*)(bias + (size_t)l * 512 + col);
                float2 v;
                v.x = c[mt][nt][2 * i + 0] + bvv.x;
                v.y = c[mt][nt][2 * i + 1] + bvv.y;
                cs[nt * 2 + 0] += v.x; cq[nt * 2 + 0] += v.x * v.x;
                cs[nt * 2 + 1] += v.y; cq[nt * 2 + 1] += v.y * v.y;
                *(float2*)(C + (size_t)row * 512 + col) = v;
            }
        }
    colstats_epilogue(ssum, ssq, cs, cq, g, t, bc + wn);
}

// Batched NT: C[k,q] = sum_e k2[k,e]*q2[q,e] + wbT. Both m-major. Row stats fused.
__global__ void __launch_bounds__(128) k_gemm_nt(const float* __restrict__ Ain,
                                                 const float* __restrict__ Bin,
                                                 const float* __restrict__ wbT,
                                                 float* __restrict__ Cout,
                                                 float* __restrict__ rsum,
                                                 float* __restrict__ rsq) {
    const int bz = blockIdx.z;
    const float* A = Ain + (size_t)bz * Ll * Ee;
    const float* Bm = Bin + (size_t)bz * Ll * Ee;
    float* C = Cout + (size_t)bz * Ll * Ll;
    __shared__ uint32_t As[2][16][PADW];
    __shared__ uint32_t Bs[2][16][PADW];
    float c[4][8][4] = {{{0.f}}};
    const int tid = threadIdx.x;
    const int lane = tid & 31, wid = tid >> 5;
    const int g = lane >> 2, t = lane & 3;
    const int wm = (wid & 1) << 6, wn = (wid >> 1) << 6;
    const int br = blockIdx.y << 7, bc = blockIdx.x << 7;
    const int lm = tid >> 2, lk4 = (tid & 3) << 2, sw = (tid & 3) << 3;

    float4 av[4], bv[4];
    #pragma unroll
    for (int rr = 0; rr < 4; rr++) {
        const int m = lm + (rr << 5);
        av[rr] = *(const float4*)(A + (size_t)(br + m) * 512 + lk4);
        bv[rr] = *(const float4*)(Bm + (size_t)(bc + m) * 512 + lk4);
    }
    #pragma unroll
    for (int rr = 0; rr < 4; rr++) {
        stA(As[0], lk4, lm + (rr << 5), sw, av[rr]);
        stA(Bs[0], lk4, lm + (rr << 5), sw, bv[rr]);
    }

    const int nIter = 32;
    for (int i = 0; i < nIter; i++) {
        const int buf = i & 1, nb = buf ^ 1;
        __syncthreads();
        const int k1 = (i + 1) << 4;
        if (i + 1 < nIter) {
            #pragma unroll
            for (int rr = 0; rr < 4; rr++) {
                const int m = lm + (rr << 5);
                av[rr] = *(const float4*)(A + (size_t)(br + m) * 512 + k1 + lk4);
                bv[rr] = *(const float4*)(Bm + (size_t)(bc + m) * 512 + k1 + lk4);
            }
        }
        mma_core64(As[buf], Bs[buf], c, g, t, wm, wn);
        if (i + 1 < nIter) {
            #pragma unroll
            for (int rr = 0; rr < 4; rr++) {
                stA(As[nb], lk4, lm + (rr << 5), sw, av[rr]);
                stA(Bs[nb], lk4, lm + (rr << 5), sw, bv[rr]);
            }
        }
    }

    float rs[8] = {0.f}, rq[8] = {0.f};
    #pragma unroll
    for (int mt = 0; mt < 4; mt++)
        #pragma unroll
        for (int i = 0; i < 2; i++) {
            const int row = br + wm + mt * 16 + g + 8 * i;   // k
            #pragma unroll
            for (int nt = 0; nt < 8; nt++) {
                const int col = bc + wn + nt * 8 + 2 * t;    // q
                float2 bv2 = *(const float2*)(wbT + (size_t)row * 512 + col);
                float2 v;
                v.x = c[mt][nt][2 * i + 0] + bv2.x;
                v.y = c[mt][nt][2 * i + 1] + bv2.y;
                rs[mt * 2 + i] += v.x + v.y;
                rq[mt * 2 + i] += v.x * v.x + v.y * v.y;
                *(float2*)(C + (size_t)row * 512 + col) = v;
            }
        }
    #pragma unroll
    for (int x = 0; x < 8; x++) {
        float s = rs[x], q = rq[x];
        s += __shfl_xor_sync(0xffffffffu, s, 1); q += __shfl_xor_sync(0xffffffffu, q, 1);
        s += __shfl_xor_sync(0xffffffffu, s, 2); q += __shfl_xor_sync(0xffffffffu, q, 2);
        if (t == 0) {
            const int row = br + wm + (x >> 1) * 16 + g + 8 * (x & 1);
            atomicAdd(&rsum[row], s);
            atomicAdd(&rsq[row], q);
        }
    }
}

// Batched TN: C[q,e] = sum_k wT[k,q]*l[k,e]. Both k-major. Col stats fused.
__global__ void __launch_bounds__(128) k_gemm_tn(const float* __restrict__ Ain,
                                                 const float* __restrict__ Bin,
                                                 float* __restrict__ Cout,
                                                 float* __restrict__ ssum,
                                                 float* __restrict__ ssq) {
    const int bz = blockIdx.z;
    const float* A = Ain + (size_t)bz * Ll * Ll;
    const float* Bm = Bin + (size_t)bz * Ll * Ee;
    float* C = Cout + (size_t)bz * Ll * Ee;
    __shared__ uint32_t As[2][16][PADW];
    __shared__ uint32_t Bs[2][16][PADW];
    float c[4][8][4] = {{{0.f}}};
    const int tid = threadIdx.x;
    const int lane = tid & 31, wid = tid >> 5;
    const int g = lane >> 2, t = lane & 3;
    const int wm = (wid & 1) << 6, wn = (wid >> 1) << 6;
    const int br = blockIdx.y << 7, bc = blockIdx.x << 7;
    const int lkb = tid >> 5, ln4 = lane << 2;

    float4 av[4], bv[4];
    #pragma unroll
    for (int rr = 0; rr < 4; rr++) {
        const int kk = lkb + (rr << 2);
        av[rr] = *(const float4*)(A + (size_t)kk * 512 + br + ln4);
        bv[rr] = *(const float4*)(Bm + (size_t)kk * 512 + bc + ln4);
    }
    #pragma unroll
    for (int rr = 0; rr < 4; rr++) {
        stB(As[0], lkb + (rr << 2), ln4, av[rr]);
        stB(Bs[0], lkb + (rr << 2), ln4, bv[rr]);
    }

    const int nIter = 32;
    for (int i = 0; i < nIter; i++) {
        const int buf = i & 1, nb = buf ^ 1;
        __syncthreads();
        const int k1 = (i + 1) << 4;
        if (i + 1 < nIter) {
            #pragma unroll
            for (int rr = 0; rr < 4; rr++) {
                const int kk = k1 + lkb + (rr << 2);
                av[rr] = *(const float4*)(A + (size_t)kk * 512 + br + ln4);
                bv[rr] = *(const float4*)(Bm + (size_t)kk * 512 + bc + ln4);
            }
        }
        mma_core64(As[buf], Bs[buf], c, g, t, wm, wn);
        if (i + 1 < nIter) {
            #pragma unroll
            for (int rr = 0; rr < 4; rr++) {
                stB(As[nb], lkb + (rr << 2), ln4, av[rr]);
                stB(Bs[nb], lkb + (rr << 2), ln4, bv[rr]);
            }
        }
    }

    float cs[16] = {0.f}, cq[16] = {0.f};
    #pragma unroll
    for (int mt = 0; mt < 4; mt++)
        #pragma unroll
        for (int i = 0; i < 2; i++) {
            const int row = br + wm + mt * 16 + g + 8 * i;
            #pragma unroll
            for (int nt = 0; nt < 8; nt++) {
                const int col = bc + wn + nt * 8 + 2 * t;
                float2 v;
                v.x = c[mt][nt][2 * i + 0];
                v.y = c[mt][nt][2 * i + 1];
                cs[nt * 2 + 0] += v.x; cq[nt * 2 + 0] += v.x * v.x;
                cs[nt * 2 + 1] += v.y; cq[nt * 2 + 1] += v.y * v.y;
                *(float2*)(C + (size_t)row * 512 + col) = v;
            }
        }
    colstats_epilogue(ssum, ssq, cs, cq, g, t, bc + wn);
}

extern "C" void kernel_launch(void* const* d_in, const int* in_sizes, int n_in,
                              void* d_out, int out_size) {
    const float* m1 = (const float*)d_in[0];
    const float* f  = (const float*)d_in[1];
    const float* wq = (const float*)d_in[2];
    const float* wk = (const float*)d_in[3];
    const float* qb = (const float*)d_in[4];
    const float* kb = (const float*)d_in[5];
    const float* wb = (const float*)d_in[6];
    const float* g1 = (const float*)d_in[7];  const float* b1 = (const float*)d_in[8];
    const float* g2 = (const float*)d_in[9];  const float* b2 = (const float*)d_in[10];
    const float* g3 = (const float*)d_in[11]; const float* b3 = (const float*)d_in[12];
    const float* g4 = (const float*)d_in[13]; const float* b4 = (const float*)d_in[14];
    const float* g5 = (const float*)d_in[15]; const float* b5 = (const float*)d_in[16];

    float *pl, *pq, *pk, *pw, *po, *ps, *pwbT, *pfr, *pwqr, *pwkr;
    cudaGetSymbolAddress((void**)&pl, g_l);
    cudaGetSymbolAddress((void**)&pq, g_q);
    cudaGetSymbolAddress((void**)&pk, g_k);
    cudaGetSymbolAddress((void**)&pw, g_w);
    cudaGetSymbolAddress((void**)&po, g_o);
    cudaGetSymbolAddress((void**)&ps, g_s);
    cudaGetSymbolAddress((void**)&pwbT, g_wbT);
    cudaGetSymbolAddress((void**)&pfr, g_fr);
    cudaGetSymbolAddress((void**)&pwqr, g_wqr);
    cudaGetSymbolAddress((void**)&pwkr, g_wkr);

    const int T = 256, TG = 128;

    k_zero<<<20, T>>>(ps, 10 * Ee);
    k_transpose<<<dim3(16, 16), dim3(32, 8)>>>(wb, pwbT);
    k_round<<<1280, T>>>(f, pfr, KE * Ee / 4);
    k_round<<<256, T>>>(wq, pwqr, Ee * Ee / 4);
    k_round<<<256, T>>>(wk, pwkr, Ee * Ee / 4);

    k_gemm1<<<dim3(4, 128), TG>>>(m1, pfr, kb, pl, ps + 0 * Ee, ps + 1 * Ee);
    k_bn_elu<true><<<2048, T>>>((const float4*)pl, (float4*)pl,
                                (const float4*)(ps + 0 * Ee), (const float4*)(ps + 1 * Ee),
                                (const float4*)g1, (const float4*)b1);

    k_gemm_nn<<<dim3(4, 128, 2), TG>>>(pl, pwqr, pwkr, qb, kb, pq, pk, ps);
    k_bn_elu<true><<<2048, T>>>((const float4*)pq, (float4*)pq,
                                (const float4*)(ps + 2 * Ee), (const float4*)(ps + 3 * Ee),
                                (const float4*)g2, (const float4*)b2);
    k_bn_elu<true><<<2048, T>>>((const float4*)pk, (float4*)pk,
                                (const float4*)(ps + 4 * Ee), (const float4*)(ps + 5 * Ee),
                                (const float4*)g3, (const float4*)b3);

    k_gemm_nt<<<dim3(4, 4, 32), TG>>>(pk, pq, pwbT, pw, ps + 8 * Ee, ps + 9 * Ee);
    k_bn_softmax<<<16384, T>>>(pw, ps + 8 * Ee, ps + 9 * Ee, g4, b4);

    k_gemm_tn<<<dim3(4, 4, 32), TG>>>(pw, pl, po, ps + 6 * Ee, ps + 7 * Ee);
    k_bn_elu<false><<<2048, T>>>((const float4*)po, (float4*)d_out,
                                 (const float4*)(ps + 6 * Ee), (const float4*)(ps + 7 * Ee),
                                 (const float4*)g5, (const float4*)b5);
}

// round 10
// speedup vs baseline: 3.7869x; 1.3648x over previous
#include <cuda_runtime.h>
#include <cuda_fp16.h>
#include <math.h>
#include <stdint.h>

#define Bb 32
#define Ll 512
#define Ee 512
#define RR (Bb*Ll)
#define KE (5*Ee)
#define EPSV 1e-3f
#define PADW 136

// fp32 scratch (pre-BN activations for exact stats)
__device__ float g_l[RR*Ee];
__device__ float g_q[RR*Ee];
__device__ float g_k[RR*Ee];
__device__ float g_w[Bb*Ll*Ll];     // wT[b,k,q] pre-BN fp32
__device__ float g_o[RR*Ee];
__device__ float g_wbT[Ll*Ll];
__device__ float g_s[10*Ee];
// fp16 operands
__device__ __half g_m1h[RR*Ee];
__device__ __half g_fh[KE*Ee];
__device__ __half g_wqh[Ee*Ee];
__device__ __half g_wkh[Ee*Ee];
__device__ __half g_lh[RR*Ee];
__device__ __half g_qh[RR*Ee];
__device__ __half g_kh[RR*Ee];
__device__ __half g_wh[Bb*Ll*Ll];

__device__ __forceinline__ uint32_t pack2(float a, float b) {
    __half2 h = __floats2half2_rn(a, b);
    return *(uint32_t*)&h;
}

// ---------------------------------------------------------------------------
// fp16 mma core: 64x64 warp tile over [16][PADW] kpair-word tiles, BK=32.
// word (kp, col) = {X[2kp][col], X[2kp+1][col]} (A: col=m; B: col=n).
// ---------------------------------------------------------------------------
__device__ __forceinline__ void mma_core64h(const uint32_t (*As)[PADW],
                                            const uint32_t (*Bs)[PADW],
                                            float c[4][8][4],
                                            int g, int t, int wm, int wn) {
    #pragma unroll
    for (int ks = 0; ks < 2; ks++) {
        const int kb = ks * 8;
        uint32_t a[4][4], b[8][2];
        #pragma unroll
        for (int mt = 0; mt < 4; mt++) {
            const int m = wm + mt * 16 + g;
            a[mt][0] = As[kb + t][m];
            a[mt][1] = As[kb + t][m + 8];
            a[mt][2] = As[kb + t + 4][m];
            a[mt][3] = As[kb + t + 4][m + 8];
        }
        #pragma unroll
        for (int nt = 0; nt < 8; nt++) {
            const int n = wn + nt * 8 + g;
            b[nt][0] = Bs[kb + t][n];
            b[nt][1] = Bs[kb + t + 4][n];
        }
        #pragma unroll
        for (int mt = 0; mt < 4; mt++)
            #pragma unroll
            for (int nt = 0; nt < 8; nt++)
                asm volatile(
                    "mma.sync.aligned.m16n8k16.row.col.f32.f16.f16.f32 "
                    "{%0,%1,%2,%3},{%4,%5,%6,%7},{%8,%9},{%0,%1,%2,%3};"
                    : "+f"(c[mt][nt][0]), "+f"(c[mt][nt][1]),
                      "+f"(c[mt][nt][2]), "+f"(c[mt][nt][3])
                    : "r"(a[mt][0]), "r"(a[mt][1]), "r"(a[mt][2]), "r"(a[mt][3]),
                      "r"(b[nt][0]), "r"(b[nt][1]));
    }
}

// m-major staging: thread col m = tid, 32 k-contig halves = 4 x uint4.
__device__ __forceinline__ void ld_mmaj(uint4 v[4], const __half* src) {
    const uint4* p = (const uint4*)src;
    v[0] = p[0]; v[1] = p[1]; v[2] = p[2]; v[3] = p[3];
}
__device__ __forceinline__ void st_mmaj(uint32_t (*S)[PADW], int m, const uint4 v[4]) {
    #pragma unroll
    for (int u = 0; u < 4; u++) {
        S[4*u + 0][m] = v[u].x;
        S[4*u + 1][m] = v[u].y;
        S[4*u + 2][m] = v[u].z;
        S[4*u + 3][m] = v[u].w;
    }
}
// k-major staging: thread covers colquad c0 = 4*(tid&31), kp = (tid>>5)+4j.
__device__ __forceinline__ void ld_kmaj(uint2 x[4], uint2 y[4], const __half* B,
                                        int ld, int k0, int kpb, int gcol) {
    #pragma unroll
    for (int j = 0; j < 4; j++) {
        const __half* r = B + (size_t)(k0 + 2 * (kpb + 4 * j)) * ld + gcol;
        x[j] = *(const uint2*)r;
        y[j] = *(const uint2*)(r + ld);
    }
}
__device__ __forceinline__ void st_kmaj(uint32_t (*S)[PADW], int kpb, int c0,
                                        const uint2 x[4], const uint2 y[4]) {
    #pragma unroll
    for (int j = 0; j < 4; j++) {
        const int kp = kpb + 4 * j;
        uint4 w;
        w.x = __byte_perm(x[j].x, y[j].x, 0x5410);
        w.y = __byte_perm(x[j].x, y[j].x, 0x7632);
        w.z = __byte_perm(x[j].y, y[j].y, 0x5410);
        w.w = __byte_perm(x[j].y, y[j].y, 0x7632);
        *(uint4*)&S[kp][c0] = w;
    }
}

__device__ __forceinline__ void colstats_epilogue(float* __restrict__ sum,
                                                  float* __restrict__ sumsq,
                                                  const float cs[16], const float cq[16],
                                                  int g, int t, int bcwn) {
    #pragma unroll
    for (int x = 0; x < 16; x++) {
        float s = cs[x], q = cq[x];
        s += __shfl_xor_sync(0xffffffffu, s, 4);  q += __shfl_xor_sync(0xffffffffu, q, 4);
        s += __shfl_xor_sync(0xffffffffu, s, 8);  q += __shfl_xor_sync(0xffffffffu, q, 8);
        s += __shfl_xor_sync(0xffffffffu, s, 16); q += __shfl_xor_sync(0xffffffffu, q, 16);
        if (g == 0) {
            const int col = bcwn + (x >> 1) * 8 + 2 * t + (x & 1);
            atomicAdd(&sum[col], s);
            atomicAdd(&sumsq[col], q);
        }
    }
}
__device__ __forceinline__ float blockReduceSum(float v, float* sh) {
    const int t = threadIdx.x;
    #pragma unroll
    for (int o = 16; o > 0; o >>= 1) v += __shfl_xor_sync(0xffffffffu, v, o);
    if ((t & 31) == 0) sh[t >> 5] = v;
    __syncthreads();
    if (t < 32) {
        v = (t < (int)(blockDim.x >> 5)) ? sh[t] : 0.f;
        #pragma unroll
        for (int o = 16; o > 0; o >>= 1) v += __shfl_xor_sync(0xffffffffu, v, o);
        if (t == 0) sh[0] = v;
    }
    __syncthreads();
    float r = sh[0];
    __syncthreads();
    return r;
}
__device__ __forceinline__ float blockReduceMax(float v, float* sh) {
    const int t = threadIdx.x;
    #pragma unroll
    for (int o = 16; o > 0; o >>= 1) v = fmaxf(v, __shfl_xor_sync(0xffffffffu, v, o));
    if ((t & 31) == 0) sh[t >> 5] = v;
    __syncthreads();
    if (t < 32) {
        v = (t < (int)(blockDim.x >> 5)) ? sh[t] : -INFINITY;
        #pragma unroll
        for (int o = 16; o > 0; o >>= 1) v = fmaxf(v, __shfl_xor_sync(0xffffffffu, v, o));
        if (t == 0) sh[0] = v;
    }
    __syncthreads();
    float r = sh[0];
    __syncthreads();
    return r;
}

__global__ void k_zero(float* p, int n) {
    int i = blockIdx.x * blockDim.x + threadIdx.x;
    if (i < n) p[i] = 0.f;
}
__global__ void k_transpose(const float* __restrict__ src, float* __restrict__ dst) {
    __shared__ float tile[32][33];
    const int bx = blockIdx.x << 5, by = blockIdx.y << 5;
    #pragma unroll
    for (int j = 0; j < 4; j++)
        tile[threadIdx.y + j * 8][threadIdx.x] =
            src[(size_t)(by + threadIdx.y + j * 8) * 512 + bx + threadIdx.x];
    __syncthreads();
    #pragma unroll
    for (int j = 0; j < 4; j++)
        dst[(size_t)(bx + threadIdx.y + j * 8) * 512 + by + threadIdx.x] =
            tile[threadIdx.x][threadIdx.y + j * 8];
}
__global__ void k_tohalf(const float4* __restrict__ src, uint2* __restrict__ dst, int n4) {
    int i = blockIdx.x * blockDim.x + threadIdx.x;
    if (i < n4) {
        float4 v = src[i];
        uint2 o;
        o.x = pack2(v.x, v.y);
        o.y = pack2(v.z, v.w);
        dst[i] = o;
    }
}

// BN + ELU; HOUT: write half, else fp32.
template<bool HOUT>
__global__ void __launch_bounds__(256) k_bn_elu(const float4* __restrict__ X,
                                                void* __restrict__ Y,
                                                const float4* __restrict__ sum4,
                                                const float4* __restrict__ sumsq4,
                                                const float4* __restrict__ g4,
                                                const float4* __restrict__ bt4) {
    const float invN = 1.f / (float)RR;
    const int total4 = RR * Ee / 4;
    for (int i = blockIdx.x * blockDim.x + threadIdx.x; i < total4;
         i += gridDim.x * blockDim.x) {
        const int c4 = i & 127;
        float4 sm = sum4[c4], sq = sumsq4[c4], gg = g4[c4], bb = bt4[c4];
        float4 v = X[i];
        float m, va, sc, y;
        float4 o;
        m = sm.x * invN; va = sq.x * invN - m * m; sc = gg.x * rsqrtf(va + EPSV);
        y = (v.x - m) * sc + bb.x; o.x = y > 0.f ? y : expm1f(y);
        m = sm.y * invN; va = sq.y * invN - m * m; sc = gg.y * rsqrtf(va + EPSV);
        y = (v.y - m) * sc + bb.y; o.y = y > 0.f ? y : expm1f(y);
        m = sm.z * invN; va = sq.z * invN - m * m; sc = gg.z * rsqrtf(va + EPSV);
        y = (v.z - m) * sc + bb.z; o.z = y > 0.f ? y : expm1f(y);
        m = sm.w * invN; va = sq.w * invN - m * m; sc = gg.w * rsqrtf(va + EPSV);
        y = (v.w - m) * sc + bb.w; o.w = y > 0.f ? y : expm1f(y);
        if (HOUT) {
            uint2 u;
            u.x = pack2(o.x, o.y);
            u.y = pack2(o.z, o.w);
            ((uint2*)Y)[i] = u;
        } else {
            ((float4*)Y)[i] = o;
        }
    }
}

// BN4 + softmax over q; reads fp32 wT rows, writes half. Thread -> cols 2t,2t+1.
__global__ void k_bn_softmax(const float* __restrict__ Wt, __half* __restrict__ Wh,
                             const float* __restrict__ sum, const float* __restrict__ sumsq,
                             const float* __restrict__ g4, const float* __restrict__ b4) {
    const int bk = blockIdx.x;
    const int k = bk & 511;
    const float* row = Wt + ((size_t)bk << 9);
    const float invN = 1.f / (float)RR;
    const float mean = sum[k] * invN;
    const float var = sumsq[k] * invN - mean * mean;
    const float sc = g4[k] * rsqrtf(var + EPSV);
    const float shf = b4[k] - mean * sc;
    const int t = threadIdx.x;
    float2 xv = *(const float2*)(row + 2 * t);
    float x0 = xv.x * sc + shf;
    float x1 = xv.y * sc + shf;
    __shared__ float sh[32];
    float mx = blockReduceMax(fmaxf(x0, x1), sh);
    float e0 = expf(x0 - mx), e1 = expf(x1 - mx);
    float tot = blockReduceSum(e0 + e1, sh);
    float inv = 1.f / tot;
    *(uint32_t*)(Wh + ((size_t)bk << 9) + 2 * t) = pack2(e0 * inv, e1 * inv);
}

// ---------------------------------------------------------------------------
// fp16 GEMMs: 128x128 C tile, BK=32, 128 threads (4 warps 2x2), 64x64 warp
// tiles, register double-buffered smem, one sync/iter, stats fused.
// ---------------------------------------------------------------------------

// GEMM1: C = unfold(m1h) @ fh + kb. A gathered m-major, B k-major. Col stats.
__global__ void __launch_bounds__(128) k_gemm1(const __half* __restrict__ Ah,
                                               const __half* __restrict__ Bh,
                                               const float* __restrict__ kb,
                                               float* __restrict__ C,
                                               float* __restrict__ ssum,
                                               float* __restrict__ ssq) {
    __shared__ uint32_t As[2][16][PADW];
    __shared__ uint32_t Bs[2][16][PADW];
    float c[4][8][4] = {{{0.f}}};
    const int tid = threadIdx.x;
    const int lane = tid & 31, wid = tid >> 5;
    const int g = lane >> 2, t = lane & 3;
    const int wm = (wid & 1) << 6, wn = (wid >> 1) << 6;
    const int br = blockIdx.y << 7, bc = blockIdx.x << 7;
    const int kpb = tid >> 5, c0 = (tid & 31) << 2;

    const int row = br + tid;
    const int bA = row >> 9, lA = row & 511;

    uint4 av[4];
    uint2 bx[4], by[4];
    {
        const int sl = lA - 2;
        if ((unsigned)sl < 512u)
            ld_mmaj(av, Ah + (((size_t)(bA << 9) + sl) << 9));
        else
            av[0] = av[1] = av[2] = av[3] = make_uint4(0, 0, 0, 0);
        ld_kmaj(bx, by, Bh, Ee, 0, kpb, bc + c0);
    }
    st_mmaj(As[0], tid, av);
    st_kmaj(Bs[0], kpb, c0, bx, by);

    const int nIter = KE / 32;
    for (int i = 0; i < nIter; i++) {
        const int buf = i & 1, nb = buf ^ 1;
        __syncthreads();
        const int k1 = (i + 1) << 5;
        if (i + 1 < nIter) {
            const int sl = lA + (k1 >> 9) - 2;
            if ((unsigned)sl < 512u)
                ld_mmaj(av, Ah + (((size_t)(bA << 9) + sl) << 9) + (k1 & 511));
            else
                av[0] = av[1] = av[2] = av[3] = make_uint4(0, 0, 0, 0);
            ld_kmaj(bx, by, Bh, Ee, k1, kpb, bc + c0);
        }
        mma_core64h(As[buf], Bs[buf], c, g, t, wm, wn);
        if (i + 1 < nIter) {
            st_mmaj(As[nb], tid, av);
            st_kmaj(Bs[nb], kpb, c0, bx, by);
        }
    }

    float cs[16] = {0.f}, cq[16] = {0.f};
    #pragma unroll
    for (int mt = 0; mt < 4; mt++)
        #pragma unroll
        for (int i = 0; i < 2; i++) {
            const int rowo = br + wm + mt * 16 + g + 8 * i;
            const int l = rowo & 511;
            #pragma unroll
            for (int nt = 0; nt < 8; nt++) {
                const int col = bc + wn + nt * 8 + 2 * t;
                float2 bvv = *(const float2*)(kb + (size_t)l * 512 + col);
                float2 v;
                v.x = c[mt][nt][2 * i + 0] + bvv.x;
                v.y = c[mt][nt][2 * i + 1] + bvv.y;
                cs[nt * 2 + 0] += v.x; cq[nt * 2 + 0] += v.x * v.x;
                cs[nt * 2 + 1] += v.y; cq[nt * 2 + 1] += v.y * v.y;
                *(float2*)(C + (size_t)rowo * 512 + col) = v;
            }
        }
    colstats_epilogue(ssum, ssq, cs, cq, g, t, bc + wn);
}

// Fused NN GEMMs (z=0: q2 = l@wq + qb ; z=1: k2 = l@wk + kb). Col stats fused.
__global__ void __launch_bounds__(128) k_gemm_nn(const __half* __restrict__ Ah,
                                                 const __half* __restrict__ Bqh,
                                                 const __half* __restrict__ Bkh,
                                                 const float* __restrict__ biasq,
                                                 const float* __restrict__ biask,
                                                 float* __restrict__ Cq,
                                                 float* __restrict__ Ck,
                                                 float* __restrict__ stats) {
    const __half* Bh = blockIdx.z ? Bkh : Bqh;
    const float* bias = blockIdx.z ? biask : biasq;
    float* C = blockIdx.z ? Ck : Cq;
    float* ssum = stats + (blockIdx.z ? 4 * Ee : 2 * Ee);
    float* ssq = ssum + Ee;
    __shared__ uint32_t As[2][16][PADW];
    __shared__ uint32_t Bs[2][16][PADW];
    float c[4][8][4] = {{{0.f}}};
    const int tid = threadIdx.x;
    const int lane = tid & 31, wid = tid >> 5;
    const int g = lane >> 2, t = lane & 3;
    const int wm = (wid & 1) << 6, wn = (wid >> 1) << 6;
    const int br = blockIdx.y << 7, bc = blockIdx.x << 7;
    const int kpb = tid >> 5, c0 = (tid & 31) << 2;

    uint4 av[4];
    uint2 bx[4], by[4];
    ld_mmaj(av, Ah + (size_t)(br + tid) * 512);
    ld_kmaj(bx, by, Bh, 512, 0, kpb, bc + c0);
    st_mmaj(As[0], tid, av);
    st_kmaj(Bs[0], kpb, c0, bx, by);

    const int nIter = 16;
    for (int i = 0; i < nIter; i++) {
        const int buf = i & 1, nb = buf ^ 1;
        __syncthreads();
        const int k1 = (i + 1) << 5;
        if (i + 1 < nIter) {
            ld_mmaj(av, Ah + (size_t)(br + tid) * 512 + k1);
            ld_kmaj(bx, by, Bh, 512, k1, kpb, bc + c0);
        }
        mma_core64h(As[buf], Bs[buf], c, g, t, wm, wn);
        if (i + 1 < nIter) {
            st_mmaj(As[nb], tid, av);
            st_kmaj(Bs[nb], kpb, c0, bx, by);
        }
    }

    float cs[16] = {0.f}, cq[16] = {0.f};
    #pragma unroll
    for (int mt = 0; mt < 4; mt++)
        #pragma unroll
        for (int i = 0; i < 2; i++) {
            const int rowo = br + wm + mt * 16 + g + 8 * i;
            const int l = rowo & 511;
            #pragma unroll
            for (int nt = 0; nt < 8; nt++) {
                const int col = bc + wn + nt * 8 + 2 * t;
                float2 bvv = *(const float2*)(bias + (size_t)l * 512 + col);
                float2 v;
                v.x = c[mt][nt][2 * i + 0] + bvv.x;
                v.y = c[mt][nt][2 * i + 1] + bvv.y;
                cs[nt * 2 + 0] += v.x; cq[nt * 2 + 0] += v.x * v.x;
                cs[nt * 2 + 1] += v.y; cq[nt * 2 + 1] += v.y * v.y;
                *(float2*)(C + (size_t)rowo * 512 + col) = v;
            }
        }
    colstats_epilogue(ssum, ssq, cs, cq, g, t, bc + wn);
}

// Batched NT: C[k,q] = sum_e k2[k,e]*q2[q,e] + wbT. Both m-major. Row stats.
__global__ void __launch_bounds__(128) k_gemm_nt(const __half* __restrict__ Ain,
                                                 const __half* __restrict__ Bin,
                                                 const float* __restrict__ wbT,
                                                 float* __restrict__ Cout,
                                                 float* __restrict__ rsum,
                                                 float* __restrict__ rsq) {
    const int bz = blockIdx.z;
    const __half* A = Ain + (size_t)bz * Ll * Ee;
    const __half* Bm = Bin + (size_t)bz * Ll * Ee;
    float* C = Cout + (size_t)bz * Ll * Ll;
    __shared__ uint32_t As[2][16][PADW];
    __shared__ uint32_t Bs[2][16][PADW];
    float c[4][8][4] = {{{0.f}}};
    const int tid = threadIdx.x;
    const int lane = tid & 31, wid = tid >> 5;
    const int g = lane >> 2, t = lane & 3;
    const int wm = (wid & 1) << 6, wn = (wid >> 1) << 6;
    const int br = blockIdx.y << 7, bc = blockIdx.x << 7;

    uint4 av[4], bv[4];
    ld_mmaj(av, A + (size_t)(br + tid) * 512);
    ld_mmaj(bv, Bm + (size_t)(bc + tid) * 512);
    st_mmaj(As[0], tid, av);
    st_mmaj(Bs[0], tid, bv);

    const int nIter = 16;
    for (int i = 0; i < nIter; i++) {
        const int buf = i & 1, nb = buf ^ 1;
        __syncthreads();
        const int k1 = (i + 1) << 5;
        if (i + 1 < nIter) {
            ld_mmaj(av, A + (size_t)(br + tid) * 512 + k1);
            ld_mmaj(bv, Bm + (size_t)(bc + tid) * 512 + k1);
        }
        mma_core64h(As[buf], Bs[buf], c, g, t, wm, wn);
        if (i + 1 < nIter) {
            st_mmaj(As[nb], tid, av);
            st_mmaj(Bs[nb], tid, bv);
        }
    }

    float rs[8] = {0.f}, rq[8] = {0.f};
    #pragma unroll
    for (int mt = 0; mt < 4; mt++)
        #pragma unroll
        for (int i = 0; i < 2; i++) {
            const int rowo = br + wm + mt * 16 + g + 8 * i;
            #pragma unroll
            for (int nt = 0; nt < 8; nt++) {
                const int col = bc + wn + nt * 8 + 2 * t;
                float2 bv2 = *(const float2*)(wbT + (size_t)rowo * 512 + col);
                float2 v;
                v.x = c[mt][nt][2 * i + 0] + bv2.x;
                v.y = c[mt][nt][2 * i + 1] + bv2.y;
                rs[mt * 2 + i] += v.x + v.y;
                rq[mt * 2 + i] += v.x * v.x + v.y * v.y;
                *(float2*)(C + (size_t)rowo * 512 + col) = v;
            }
        }
    #pragma unroll
    for (int x = 0; x < 8; x++) {
        float s = rs[x], q = rq[x];
        s += __shfl_xor_sync(0xffffffffu, s, 1); q += __shfl_xor_sync(0xffffffffu, q, 1);
        s += __shfl_xor_sync(0xffffffffu, s, 2); q += __shfl_xor_sync(0xffffffffu, q, 2);
        if (t == 0) {
            const int rowo = br + wm + (x >> 1) * 16 + g + 8 * (x & 1);
            atomicAdd(&rsum[rowo], s);
            atomicAdd(&rsq[rowo], q);
        }
    }
}

// Batched TN: C[q,e] = sum_k wh[k,q]*lh[k,e]. Both k-major. Col stats fused.
__global__ void __launch_bounds__(128) k_gemm_tn(const __half* __restrict__ Ain,
                                                 const __half* __restrict__ Bin,
                                                 float* __restrict__ Cout,
                                                 float* __restrict__ ssum,
                                                 float* __restrict__ ssq) {
    const int bz = blockIdx.z;
    const __half* A = Ain + (size_t)bz * Ll * Ll;
    const __half* Bm = Bin + (size_t)bz * Ll * Ee;
    float* C = Cout + (size_t)bz * Ll * Ee;
    __shared__ uint32_t As[2][16][PADW];
    __shared__ uint32_t Bs[2][16][PADW];
    float c[4][8][4] = {{{0.f}}};
    const int tid = threadIdx.x;
    const int lane = tid & 31, wid = tid >> 5;
    const int g = lane >> 2, t = lane & 3;
    const int wm = (wid & 1) << 6, wn = (wid >> 1) << 6;
    const int br = blockIdx.y << 7, bc = blockIdx.x << 7;
    const int kpb = tid >> 5, c0 = (tid & 31) << 2;

    uint2 ax[4], ay[4], bx[4], by[4];
    ld_kmaj(ax, ay, A, 512, 0, kpb, br + c0);
    ld_kmaj(bx, by, Bm, 512, 0, kpb, bc + c0);
    st_kmaj(As[0], kpb, c0, ax, ay);
    st_kmaj(Bs[0], kpb, c0, bx, by);

    const int nIter = 16;
    for (int i = 0; i < nIter; i++) {
        const int buf = i & 1, nb = buf ^ 1;
        __syncthreads();
        const int k1 = (i + 1) << 5;
        if (i + 1 < nIter) {
            ld_kmaj(ax, ay, A, 512, k1, kpb, br + c0);
            ld_kmaj(bx, by, Bm, 512, k1, kpb, bc + c0);
        }
        mma_core64h(As[buf], Bs[buf], c, g, t, wm, wn);
        if (i + 1 < nIter) {
            st_kmaj(As[nb], kpb, c0, ax, ay);
            st_kmaj(Bs[nb], kpb, c0, bx, by);
        }
    }

    float cs[16] = {0.f}, cq[16] = {0.f};
    #pragma unroll
    for (int mt = 0; mt < 4; mt++)
        #pragma unroll
        for (int i = 0; i < 2; i++) {
            const int rowo = br + wm + mt * 16 + g + 8 * i;
            #pragma unroll
            for (int nt = 0; nt < 8; nt++) {
                const int col = bc + wn + nt * 8 + 2 * t;
                float2 v;
                v.x = c[mt][nt][2 * i + 0];
                v.y = c[mt][nt][2 * i + 1];
                cs[nt * 2 + 0] += v.x; cq[nt * 2 + 0] += v.x * v.x;
                cs[nt * 2 + 1] += v.y; cq[nt * 2 + 1] += v.y * v.y;
                *(float2*)(C + (size_t)rowo * 512 + col) = v;
            }
        }
    colstats_epilogue(ssum, ssq, cs, cq, g, t, bc + wn);
}

extern "C" void kernel_launch(void* const* d_in, const int* in_sizes, int n_in,
                              void* d_out, int out_size) {
    const float* m1 = (const float*)d_in[0];
    const float* f  = (const float*)d_in[1];
    const float* wq = (const float*)d_in[2];
    const float* wk = (const float*)d_in[3];
    const float* qb = (const float*)d_in[4];
    const float* kb = (const float*)d_in[5];
    const float* wb = (const float*)d_in[6];
    const float* g1 = (const float*)d_in[7];  const float* b1 = (const float*)d_in[8];
    const float* g2 = (const float*)d_in[9];  const float* b2 = (const float*)d_in[10];
    const float* g3 = (const float*)d_in[11]; const float* b3 = (const float*)d_in[12];
    const float* g4 = (const float*)d_in[13]; const float* b4 = (const float*)d_in[14];
    const float* g5 = (const float*)d_in[15]; const float* b5 = (const float*)d_in[16];

    float *pl, *pq, *pk, *pw, *po, *ps, *pwbT;
    __half *pm1h, *pfh, *pwqh, *pwkh, *plh, *pqh, *pkh, *pwh;
    cudaGetSymbolAddress((void**)&pl, g_l);
    cudaGetSymbolAddress((void**)&pq, g_q);
    cudaGetSymbolAddress((void**)&pk, g_k);
    cudaGetSymbolAddress((void**)&pw, g_w);
    cudaGetSymbolAddress((void**)&po, g_o);
    cudaGetSymbolAddress((void**)&ps, g_s);
    cudaGetSymbolAddress((void**)&pwbT, g_wbT);
    cudaGetSymbolAddress((void**)&pm1h, g_m1h);
    cudaGetSymbolAddress((void**)&pfh, g_fh);
    cudaGetSymbolAddress((void**)&pwqh, g_wqh);
    cudaGetSymbolAddress((void**)&pwkh, g_wkh);
    cudaGetSymbolAddress((void**)&plh, g_lh);
    cudaGetSymbolAddress((void**)&pqh, g_qh);
    cudaGetSymbolAddress((void**)&pkh, g_kh);
    cudaGetSymbolAddress((void**)&pwh, g_wh);

    const int T = 256, TG = 128;

    k_zero<<<20, T>>>(ps, 10 * Ee);
    k_transpose<<<dim3(16, 16), dim3(32, 8)>>>(wb, pwbT);
    k_tohalf<<<8192, T>>>((const float4*)m1, (uint2*)pm1h, RR * Ee / 4);
    k_tohalf<<<1280, T>>>((const float4*)f, (uint2*)pfh, KE * Ee / 4);
    k_tohalf<<<256, T>>>((const float4*)wq, (uint2*)pwqh, Ee * Ee / 4);
    k_tohalf<<<256, T>>>((const float4*)wk, (uint2*)pwkh, Ee * Ee / 4);

    // 1) l_pre = unfold(m1) @ f + kb ; BN1+ELU -> half
    k_gemm1<<<dim3(4, 128), TG>>>(pm1h, pfh, kb, pl, ps + 0 * Ee, ps + 1 * Ee);
    k_bn_elu<true><<<2048, T>>>((const float4*)pl, plh,
                                (const float4*)(ps + 0 * Ee), (const float4*)(ps + 1 * Ee),
                                (const float4*)g1, (const float4*)b1);

    // 2) q2 / k2 ; BN+ELU -> half
    k_gemm_nn<<<dim3(4, 128, 2), TG>>>(plh, pwqh, pwkh, qb, kb, pq, pk, ps);
    k_bn_elu<true><<<2048, T>>>((const float4*)pq, pqh,
                                (const float4*)(ps + 2 * Ee), (const float4*)(ps + 3 * Ee),
                                (const float4*)g2, (const float4*)b2);
    k_bn_elu<true><<<2048, T>>>((const float4*)pk, pkh,
                                (const float4*)(ps + 4 * Ee), (const float4*)(ps + 5 * Ee),
                                (const float4*)g3, (const float4*)b3);

    // 3) wT = k2 @ q2^T + wbT ; BN4 + softmax -> half
    k_gemm_nt<<<dim3(4, 4, 32), TG>>>(pkh, pqh, pwbT, pw, ps + 8 * Ee, ps + 9 * Ee);
    k_bn_softmax<<<16384, T>>>(pw, pwh, ps + 8 * Ee, ps + 9 * Ee, g4, b4);

    // 4) out = wT^T @ l ; BN5 + ELU -> d_out (fp32)
    k_gemm_tn<<<dim3(4, 4, 32), TG>>>(pwh, plh, po, ps + 6 * Ee, ps + 7 * Ee);
    k_bn_elu<false><<<2048, T>>>((const float4*)po, d_out,
                                 (const float4*)(ps + 6 * Ee), (const float4*)(ps + 7 * Ee),
                                 (const float4*)g5, (const float4*)b5);
}